// round 7
// baseline (speedup 1.0000x reference)
#include <cuda_runtime.h>
#include <cuda_bf16.h>
#include <cstdint>

// ---------------------------------------------------------------------------
// Problem constants
// ---------------------------------------------------------------------------
#define N_NODES  20000
#define N_EDGES  320000
#define NUM_RELS 16
#define IN_FEAT  256
#define OUT_FEAT 256

// ---------------------------------------------------------------------------
// Device scratch (static globals: allocation-guard safe)
// ---------------------------------------------------------------------------
__device__ float g_T[(size_t)NUM_RELS * N_NODES * OUT_FEAT];           // 328 MB
__device__ __align__(16) __nv_bfloat16 g_h_hi[(size_t)N_NODES * IN_FEAT];
__device__ __align__(16) __nv_bfloat16 g_h_lo[(size_t)N_NODES * IN_FEAT];
__device__ __align__(16) __nv_bfloat16 g_wt_hi[(size_t)NUM_RELS * OUT_FEAT * IN_FEAT]; // [r][n][k]
__device__ __align__(16) __nv_bfloat16 g_wt_lo[(size_t)NUM_RELS * OUT_FEAT * IN_FEAT];

// CSR-by-dst scratch
__device__ int  g_cnt[N_NODES];
__device__ int  g_fill[N_NODES];
__device__ int  g_row[N_NODES + 1];
__device__ int2 g_es[N_EDGES];   // {src | (rel<<16), bitcast(norm)} sorted by dst

// ---------------------------------------------------------------------------
// PTX helpers (arch-agnostic: ldmatrix / mma.sync / cp.async only)
// ---------------------------------------------------------------------------
__device__ __forceinline__ uint32_t smem_u32(const void* p) {
    uint32_t a;
    asm("{ .reg .u64 t; cvta.to.shared.u64 t, %1; cvt.u32.u64 %0, t; }" : "=r"(a) : "l"(p));
    return a;
}

#define LDSM_X4(r, addr) \
    asm volatile("ldmatrix.sync.aligned.m8n8.x4.shared.b16 {%0,%1,%2,%3}, [%4];" \
        : "=r"((r)[0]), "=r"((r)[1]), "=r"((r)[2]), "=r"((r)[3]) : "r"(addr))

#define MMA_BF16(d, a, b0, b1) \
    asm volatile("mma.sync.aligned.m16n8k16.row.col.f32.bf16.bf16.f32 " \
        "{%0,%1,%2,%3}, {%4,%5,%6,%7}, {%8,%9}, {%0,%1,%2,%3};" \
        : "+f"((d)[0]), "+f"((d)[1]), "+f"((d)[2]), "+f"((d)[3]) \
        : "r"((a)[0]), "r"((a)[1]), "r"((a)[2]), "r"((a)[3]), "r"(b0), "r"(b1))

#define CP_ASYNC16(saddr, gptr, nbytes) \
    asm volatile("cp.async.cg.shared.global [%0], [%1], 16, %2;" \
        :: "r"(saddr), "l"(gptr), "r"(nbytes))
#define CP_COMMIT() asm volatile("cp.async.commit_group;" ::: "memory")
#define CP_WAIT(n)  asm volatile("cp.async.wait_group %0;" :: "n"(n) : "memory")

// ---------------------------------------------------------------------------
// Kernel A: split h into bf16 hi/lo
// ---------------------------------------------------------------------------
__global__ void split_h_kernel(const float* __restrict__ h)
{
    int i = blockIdx.x * 256 + threadIdx.x;
    if (i < N_NODES * IN_FEAT) {
        float x = h[i];
        __nv_bfloat16 a = __float2bfloat16(x);
        g_h_hi[i] = a;
        g_h_lo[i] = __float2bfloat16(x - __bfloat162float(a));
    }
}

// ---------------------------------------------------------------------------
// Kernel B: transpose + split W:  Wt[r][n][k] = W[r][k][n], bf16 hi/lo
// ---------------------------------------------------------------------------
__global__ void split_wt_kernel(const float* __restrict__ W)
{
    __shared__ float tile[32][33];
    int r  = blockIdx.z;
    int k0 = blockIdx.x * 32;
    int n0 = blockIdx.y * 32;
    tile[threadIdx.y][threadIdx.x] =
        W[(size_t)r * 65536 + (size_t)(k0 + threadIdx.y) * 256 + n0 + threadIdx.x];
    __syncthreads();
    float x = tile[threadIdx.x][threadIdx.y];   // = W[r][k0+tx][n0+ty]
    size_t oi = (size_t)r * 65536 + (size_t)(n0 + threadIdx.y) * 256 + k0 + threadIdx.x;
    __nv_bfloat16 a = __float2bfloat16(x);
    g_wt_hi[oi] = a;
    g_wt_lo[oi] = __float2bfloat16(x - __bfloat162float(a));
}

// ---------------------------------------------------------------------------
// CSR build kernels
// ---------------------------------------------------------------------------
__global__ void csr_zero_kernel()
{
    int i = blockIdx.x * 256 + threadIdx.x;
    if (i < N_NODES) { g_cnt[i] = 0; g_fill[i] = 0; }
}

__global__ void csr_hist_kernel(const int* __restrict__ dst, int E)
{
    int e = blockIdx.x * 256 + threadIdx.x;
    if (e < E) atomicAdd(&g_cnt[dst[e]], 1);
}

// Single-block exclusive scan of g_cnt -> g_row (plus total at g_row[N]).
__global__ void csr_scan_kernel()
{
    __shared__ int ssum[256];
    const int t  = threadIdx.x;
    const int CH = (N_NODES + 255) / 256;   // 79
    const int base = t * CH;

    int s = 0;
    for (int i = 0; i < CH; i++) {
        int idx = base + i;
        if (idx < N_NODES) s += g_cnt[idx];
    }
    ssum[t] = s;
    __syncthreads();
    for (int off = 1; off < 256; off <<= 1) {
        int v = (t >= off) ? ssum[t - off] : 0;
        __syncthreads();
        ssum[t] += v;
        __syncthreads();
    }
    int run = (t > 0) ? ssum[t - 1] : 0;
    for (int i = 0; i < CH; i++) {
        int idx = base + i;
        if (idx < N_NODES) { g_row[idx] = run; run += g_cnt[idx]; }
    }
    if (t == 255) g_row[N_NODES] = run;
}

__global__ void csr_fill_kernel(const int* __restrict__ src,
                                const int* __restrict__ dst,
                                const int* __restrict__ rel_type,
                                const float* __restrict__ norm, int E)
{
    int e = blockIdx.x * 256 + threadIdx.x;
    if (e < E) {
        int d = dst[e];
        int pos = g_row[d] + atomicAdd(&g_fill[d], 1);
        g_es[pos] = make_int2(src[e] | (rel_type[e] << 16), __float_as_int(norm[e]));
    }
}

// ---------------------------------------------------------------------------
// Kernel C: HMMA GEMM.  T[r] = h @ W[r] via bf16 3-term split, fp32 accum.
// CTA 128x256 (full N), 8 warps (2m x 4n), warp tile 64x64, mma.m16n8k16.
// Double-buffered cp.async, BK=32 (8 chunks of K=256).
// ---------------------------------------------------------------------------
#define BM 128
#define BN 256
#define BKC 32
#define NCHUNK (IN_FEAT / BKC)      // 8
#define A_STRIDE 80                 // 64B payload + 16B pad
#define A_TILE_B (128 * A_STRIDE)   // 10240
#define B_TILE_B (256 * A_STRIDE)   // 20480
#define OFF_AHI 0
#define OFF_ALO (1 * A_TILE_B)
#define OFF_BHI (2 * A_TILE_B)
#define OFF_BLO (2 * A_TILE_B + B_TILE_B)
#define BUF_BYTES (2 * A_TILE_B + 2 * B_TILE_B)  // 61440
#define SM_TOTAL (2 * BUF_BYTES)                 // 122880

#define M_TILES ((N_NODES + BM - 1) / BM)   // 157

__device__ __forceinline__ void load_chunk(
    uint32_t sbuf, int m0, int k0, int tid,
    const __nv_bfloat16* __restrict__ Ahi, const __nv_bfloat16* __restrict__ Alo,
    const __nv_bfloat16* __restrict__ Bhi, const __nv_bfloat16* __restrict__ Blo)
{
    // A: 128 rows x 4 16B-quads = 512 segs (x2 tiles) -> 2 iters, 2 cp each
    #pragma unroll
    for (int it = 0; it < 2; it++) {
        int seg = tid + it * 256;      // 0..511
        int row = seg >> 2;            // 0..127
        int q   = seg & 3;
        uint32_t so = (uint32_t)(row * A_STRIDE + q * 16);
        int grow = m0 + row;
        int okA  = (grow < N_NODES) ? 16 : 0;
        int garow = (grow < N_NODES) ? grow : 0;
        size_t gia = (size_t)garow * IN_FEAT + k0 + q * 8;
        CP_ASYNC16(sbuf + OFF_AHI + so, Ahi + gia, okA);
        CP_ASYNC16(sbuf + OFF_ALO + so, Alo + gia, okA);
    }
    // B: 256 rows x 4 quads = 1024 segs (x2 tiles) -> 4 iters, 2 cp each
    #pragma unroll
    for (int it = 0; it < 4; it++) {
        int seg = tid + it * 256;      // 0..1023
        int row = seg >> 2;            // 0..255
        int q   = seg & 3;
        uint32_t so = (uint32_t)(row * A_STRIDE + q * 16);
        size_t gib = (size_t)row * IN_FEAT + k0 + q * 8;
        CP_ASYNC16(sbuf + OFF_BHI + so, Bhi + gib, 16);
        CP_ASYNC16(sbuf + OFF_BLO + so, Blo + gib, 16);
    }
}

__global__ __launch_bounds__(256, 1)
void rgcn_gemm_hmma_kernel()
{
    extern __shared__ char smem[];
    const uint32_t smem_base = smem_u32(smem);
    const int tid  = threadIdx.x;
    const int wid  = tid >> 5;
    const int lane = tid & 31;
    const int wm   = wid >> 2;   // 0..1
    const int wn   = wid & 3;    // 0..3  (warp n-base = wn*64)

    const int m0  = blockIdx.x * BM;
    const int rel = blockIdx.y;

    const __nv_bfloat16* Ahi = g_h_hi;
    const __nv_bfloat16* Alo = g_h_lo;
    const __nv_bfloat16* Bhi = g_wt_hi + (size_t)rel * OUT_FEAT * IN_FEAT;
    const __nv_bfloat16* Blo = g_wt_lo + (size_t)rel * OUT_FEAT * IN_FEAT;

    float acc[4][8][4];   // mi x nf x frag  = 128 regs
    #pragma unroll
    for (int i = 0; i < 4; i++)
        #pragma unroll
        for (int j = 0; j < 8; j++)
            #pragma unroll
            for (int k = 0; k < 4; k++)
                acc[i][j][k] = 0.0f;

    // ldmatrix address patterns (non-trans x4)
    const uint32_t aoff = (uint32_t)((wm * 64 + (lane & 15)) * A_STRIDE + (lane >> 4) * 16);
    const uint32_t boff = (uint32_t)((wn * 64 + ((lane >> 4) << 3) + (lane & 7)) * A_STRIDE +
                                     ((lane >> 3) & 1) * 16);

    const uint32_t sb[2] = { smem_base, smem_base + BUF_BYTES };

    load_chunk(sb[0], m0, 0, tid, Ahi, Alo, Bhi, Blo);
    CP_COMMIT();

    for (int c = 0; c < NCHUNK; c++) {
        if (c + 1 < NCHUNK) {
            load_chunk(sb[(c + 1) & 1], m0, (c + 1) * BKC, tid, Ahi, Alo, Bhi, Blo);
            CP_COMMIT();
            CP_WAIT(1);
        } else {
            CP_WAIT(0);
        }
        __syncthreads();

        const uint32_t buf = sb[c & 1];
        #pragma unroll
        for (int s = 0; s < 2; s++) {          // two k16 steps per 32-chunk
            uint32_t Ah[4][4], Al[4][4], Bx[4][4];
            // load both A splits (kept live), B single-buffered
            #pragma unroll
            for (int mi = 0; mi < 4; mi++) {
                uint32_t ad = buf + aoff + (uint32_t)(mi * 16 * A_STRIDE + s * 32);
                LDSM_X4(Ah[mi], ad + OFF_AHI);
                LDSM_X4(Al[mi], ad + OFF_ALO);
            }
            // B_hi: terms Ah*Bh and Al*Bh
            #pragma unroll
            for (int nj = 0; nj < 4; nj++) {
                uint32_t bd = buf + boff + (uint32_t)(nj * 16 * A_STRIDE + s * 32);
                LDSM_X4(Bx[nj], bd + OFF_BHI);
            }
            #pragma unroll
            for (int mi = 0; mi < 4; mi++)
                #pragma unroll
                for (int nf = 0; nf < 8; nf++) {
                    const int nj = nf >> 1, p = (nf & 1) * 2;
                    MMA_BF16(acc[mi][nf], Ah[mi], Bx[nj][p], Bx[nj][p + 1]);
                }
            #pragma unroll
            for (int mi = 0; mi < 4; mi++)
                #pragma unroll
                for (int nf = 0; nf < 8; nf++) {
                    const int nj = nf >> 1, p = (nf & 1) * 2;
                    MMA_BF16(acc[mi][nf], Al[mi], Bx[nj][p], Bx[nj][p + 1]);
                }
            // B_lo: term Ah*Bl
            #pragma unroll
            for (int nj = 0; nj < 4; nj++) {
                uint32_t bd = buf + boff + (uint32_t)(nj * 16 * A_STRIDE + s * 32);
                LDSM_X4(Bx[nj], bd + OFF_BLO);
            }
            #pragma unroll
            for (int mi = 0; mi < 4; mi++)
                #pragma unroll
                for (int nf = 0; nf < 8; nf++) {
                    const int nj = nf >> 1, p = (nf & 1) * 2;
                    MMA_BF16(acc[mi][nf], Ah[mi], Bx[nj][p], Bx[nj][p + 1]);
                }
        }
        __syncthreads();
    }

    // Epilogue
    const int g  = lane >> 2;
    const int tg = lane & 3;
    float* C = g_T + (size_t)rel * N_NODES * OUT_FEAT;
    #pragma unroll
    for (int mi = 0; mi < 4; mi++) {
        const int row0 = m0 + wm * 64 + mi * 16 + g;
        #pragma unroll
        for (int nf = 0; nf < 8; nf++) {
            const int col = wn * 64 + nf * 8 + tg * 2;
            if (row0 < N_NODES)
                *(float2*)(C + (size_t)row0 * OUT_FEAT + col) =
                    make_float2(acc[mi][nf][0], acc[mi][nf][1]);
            if (row0 + 8 < N_NODES)
                *(float2*)(C + (size_t)(row0 + 8) * OUT_FEAT + col) =
                    make_float2(acc[mi][nf][2], acc[mi][nf][3]);
        }
    }
}

// ---------------------------------------------------------------------------
// Kernel D: atomic-free gather.  64 threads per dst node (4 floats each).
// ---------------------------------------------------------------------------
__global__ __launch_bounds__(256)
void rgcn_gather_kernel(float* __restrict__ out)
{
    const int node = blockIdx.x * 4 + (threadIdx.x >> 6);
    const int lane = threadIdx.x & 63;
    if (node >= N_NODES) return;

    const int beg = g_row[node];
    const int end = g_row[node + 1];

    float4 acc = make_float4(0.f, 0.f, 0.f, 0.f);
    int i = beg;
    for (; i + 1 < end; i += 2) {
        int2 e0 = g_es[i];
        int2 e1 = g_es[i + 1];
        int   s0 = e0.x & 0xFFFF, r0 = e0.x >> 16;
        int   s1 = e1.x & 0xFFFF, r1 = e1.x >> 16;
        float n0 = __int_as_float(e0.y);
        float n1 = __int_as_float(e1.y);
        float4 v0 = ((const float4*)(g_T + ((size_t)r0 * N_NODES + s0) * OUT_FEAT))[lane];
        float4 v1 = ((const float4*)(g_T + ((size_t)r1 * N_NODES + s1) * OUT_FEAT))[lane];
        acc.x = fmaf(v0.x, n0, acc.x); acc.y = fmaf(v0.y, n0, acc.y);
        acc.z = fmaf(v0.z, n0, acc.z); acc.w = fmaf(v0.w, n0, acc.w);
        acc.x = fmaf(v1.x, n1, acc.x); acc.y = fmaf(v1.y, n1, acc.y);
        acc.z = fmaf(v1.z, n1, acc.z); acc.w = fmaf(v1.w, n1, acc.w);
    }
    if (i < end) {
        int2 e0 = g_es[i];
        int   s0 = e0.x & 0xFFFF, r0 = e0.x >> 16;
        float n0 = __int_as_float(e0.y);
        float4 v0 = ((const float4*)(g_T + ((size_t)r0 * N_NODES + s0) * OUT_FEAT))[lane];
        acc.x = fmaf(v0.x, n0, acc.x); acc.y = fmaf(v0.y, n0, acc.y);
        acc.z = fmaf(v0.z, n0, acc.z); acc.w = fmaf(v0.w, n0, acc.w);
    }

    ((float4*)(out + (size_t)node * OUT_FEAT))[lane] = acc;
}

// ---------------------------------------------------------------------------
// Launch
// ---------------------------------------------------------------------------
extern "C" void kernel_launch(void* const* d_in, const int* in_sizes, int n_in,
                              void* d_out, int out_size)
{
    const float* h        = (const float*)d_in[0];
    const float* weight   = (const float*)d_in[1];
    const float* norm     = (const float*)d_in[2];
    const int*   src      = (const int*)d_in[3];
    const int*   dst      = (const int*)d_in[4];
    const int*   rel_type = (const int*)d_in[5];
    float*       out      = (float*)d_out;

    const int E = in_sizes[2];  // 320000

    split_h_kernel<<<(N_NODES * IN_FEAT + 255) / 256, 256>>>(h);
    split_wt_kernel<<<dim3(8, 8, NUM_RELS), dim3(32, 32)>>>(weight);

    csr_zero_kernel<<<(N_NODES + 255) / 256, 256>>>();
    csr_hist_kernel<<<(E + 255) / 256, 256>>>(dst, E);
    csr_scan_kernel<<<1, 256>>>();
    csr_fill_kernel<<<(E + 255) / 256, 256>>>(src, dst, rel_type, norm, E);

    cudaFuncSetAttribute(rgcn_gemm_hmma_kernel,
                         cudaFuncAttributeMaxDynamicSharedMemorySize, SM_TOTAL);
    rgcn_gemm_hmma_kernel<<<dim3(M_TILES, NUM_RELS), 256, SM_TOTAL>>>();

    rgcn_gather_kernel<<<(N_NODES + 3) / 4, 256>>>(out);
}

// round 8
// speedup vs baseline: 1.7908x; 1.7908x over previous
#include <cuda_runtime.h>
#include <cuda_fp16.h>
#include <cstdint>

// ---------------------------------------------------------------------------
// Problem constants
// ---------------------------------------------------------------------------
#define N_NODES  20000
#define N_EDGES  320000
#define NUM_RELS 16
#define IN_FEAT  256
#define OUT_FEAT 256

// ---------------------------------------------------------------------------
// Device scratch (static globals: allocation-guard safe)
// ---------------------------------------------------------------------------
__device__ __align__(16) __half g_T[(size_t)NUM_RELS * N_NODES * OUT_FEAT];   // 164 MB
__device__ __align__(16) __half g_h16[(size_t)N_NODES * IN_FEAT];             // 10 MB
__device__ __align__(16) __half g_wt16[(size_t)NUM_RELS * OUT_FEAT * IN_FEAT]; // [r][n][k], 2 MB

// CSR-by-dst scratch
__device__ int  g_cnt[N_NODES];
__device__ int  g_fill[N_NODES];
__device__ int  g_row[N_NODES + 1];
__device__ int2 g_es[N_EDGES];   // {src | (rel<<16), bitcast(norm)} sorted by dst

// ---------------------------------------------------------------------------
// PTX helpers (arch-agnostic: ldmatrix / mma.sync / cp.async only)
// ---------------------------------------------------------------------------
__device__ __forceinline__ uint32_t smem_u32(const void* p) {
    uint32_t a;
    asm("{ .reg .u64 t; cvta.to.shared.u64 t, %1; cvt.u32.u64 %0, t; }" : "=r"(a) : "l"(p));
    return a;
}

#define LDSM_X4(r, addr) \
    asm volatile("ldmatrix.sync.aligned.m8n8.x4.shared.b16 {%0,%1,%2,%3}, [%4];" \
        : "=r"((r)[0]), "=r"((r)[1]), "=r"((r)[2]), "=r"((r)[3]) : "r"(addr))

#define MMA_F16(d, a, b0, b1) \
    asm volatile("mma.sync.aligned.m16n8k16.row.col.f32.f16.f16.f32 " \
        "{%0,%1,%2,%3}, {%4,%5,%6,%7}, {%8,%9}, {%0,%1,%2,%3};" \
        : "+f"((d)[0]), "+f"((d)[1]), "+f"((d)[2]), "+f"((d)[3]) \
        : "r"((a)[0]), "r"((a)[1]), "r"((a)[2]), "r"((a)[3]), "r"(b0), "r"(b1))

#define CP_ASYNC16(saddr, gptr, nbytes) \
    asm volatile("cp.async.cg.shared.global [%0], [%1], 16, %2;" \
        :: "r"(saddr), "l"(gptr), "r"(nbytes))
#define CP_COMMIT() asm volatile("cp.async.commit_group;" ::: "memory")
#define CP_WAIT(n)  asm volatile("cp.async.wait_group %0;" :: "n"(n) : "memory")

// ---------------------------------------------------------------------------
// Kernel A: convert h to fp16
// ---------------------------------------------------------------------------
__global__ void conv_h_kernel(const float* __restrict__ h)
{
    int i = blockIdx.x * 256 + threadIdx.x;
    if (i < N_NODES * IN_FEAT)
        g_h16[i] = __float2half_rn(h[i]);
}

// ---------------------------------------------------------------------------
// Kernel B: transpose + convert W:  Wt[r][n][k] = W[r][k][n], fp16
// grid (8, 8, 16), block (32, 32)
// ---------------------------------------------------------------------------
__global__ void conv_wt_kernel(const float* __restrict__ W)
{
    __shared__ float tile[32][33];
    int r  = blockIdx.z;
    int k0 = blockIdx.x * 32;
    int n0 = blockIdx.y * 32;
    tile[threadIdx.y][threadIdx.x] =
        W[(size_t)r * 65536 + (size_t)(k0 + threadIdx.y) * 256 + n0 + threadIdx.x];
    __syncthreads();
    float x = tile[threadIdx.x][threadIdx.y];   // = W[r][k0+tx][n0+ty]
    size_t oi = (size_t)r * 65536 + (size_t)(n0 + threadIdx.y) * 256 + k0 + threadIdx.x;
    g_wt16[oi] = __float2half_rn(x);
}

// ---------------------------------------------------------------------------
// CSR build kernels
// ---------------------------------------------------------------------------
__global__ void csr_zero_kernel()
{
    int i = blockIdx.x * 256 + threadIdx.x;
    if (i < N_NODES) { g_cnt[i] = 0; g_fill[i] = 0; }
}

__global__ void csr_hist_kernel(const int* __restrict__ dst, int E)
{
    int e = blockIdx.x * 256 + threadIdx.x;
    if (e < E) atomicAdd(&g_cnt[dst[e]], 1);
}

// Single-block exclusive scan of g_cnt -> g_row (plus total at g_row[N]).
__global__ void csr_scan_kernel()
{
    __shared__ int ssum[256];
    const int t  = threadIdx.x;
    const int CH = (N_NODES + 255) / 256;   // 79
    const int base = t * CH;

    int s = 0;
    for (int i = 0; i < CH; i++) {
        int idx = base + i;
        if (idx < N_NODES) s += g_cnt[idx];
    }
    ssum[t] = s;
    __syncthreads();
    for (int off = 1; off < 256; off <<= 1) {
        int v = (t >= off) ? ssum[t - off] : 0;
        __syncthreads();
        ssum[t] += v;
        __syncthreads();
    }
    int run = (t > 0) ? ssum[t - 1] : 0;
    for (int i = 0; i < CH; i++) {
        int idx = base + i;
        if (idx < N_NODES) { g_row[idx] = run; run += g_cnt[idx]; }
    }
    if (t == 255) g_row[N_NODES] = run;
}

__global__ void csr_fill_kernel(const int* __restrict__ src,
                                const int* __restrict__ dst,
                                const int* __restrict__ rel_type,
                                const float* __restrict__ norm, int E)
{
    int e = blockIdx.x * 256 + threadIdx.x;
    if (e < E) {
        int d = dst[e];
        int pos = g_row[d] + atomicAdd(&g_fill[d], 1);
        g_es[pos] = make_int2(src[e] | (rel_type[e] << 16), __float_as_int(norm[e]));
    }
}

// ---------------------------------------------------------------------------
// Kernel C: single-pass fp16 HMMA GEMM.  T[r] = h @ W[r], fp32 accum, fp16 out.
// CTA 128x128, 8 warps (2m x 4n), warp tile 64x32, mma.m16n8k16.
// Double-buffered cp.async, BK=32 (8 chunks of K=256).  ~2 CTAs/SM.
// ---------------------------------------------------------------------------
#define BM 128
#define BN 128
#define BKC 32
#define NCHUNK (IN_FEAT / BKC)      // 8
#define A_STRIDE 80                 // 64B payload + 16B pad (conflict-free ldmatrix)
#define TILE_BYTES (128 * A_STRIDE) // 10240 per tile
#define OFF_A 0
#define OFF_B TILE_BYTES
#define BUF_BYTES (2 * TILE_BYTES)  // 20480
#define SM_TOTAL (2 * BUF_BYTES)    // 40960

#define M_TILES ((N_NODES + BM - 1) / BM)   // 157

__device__ __forceinline__ void load_chunk(
    uint32_t sbuf, int m0, int n0, int k0, int tid,
    const __half* __restrict__ A, const __half* __restrict__ B)
{
    // Each tile: 128 rows x 64B = 512 x 16B segments; 256 threads -> 2 each.
    #pragma unroll
    for (int it = 0; it < 2; it++) {
        int seg = tid + it * 256;      // 0..511
        int row = seg >> 2;            // 0..127
        int q   = seg & 3;             // 0..3 (16B units)
        uint32_t so = (uint32_t)(row * A_STRIDE + q * 16);
        int grow = m0 + row;
        int okA  = (grow < N_NODES) ? 16 : 0;
        int garow = (grow < N_NODES) ? grow : 0;
        CP_ASYNC16(sbuf + OFF_A + so, A + (size_t)garow * IN_FEAT + k0 + q * 8, okA);
        CP_ASYNC16(sbuf + OFF_B + so, B + (size_t)(n0 + row) * IN_FEAT + k0 + q * 8, 16);
    }
}

__global__ __launch_bounds__(256)
void rgcn_gemm_hmma_kernel()
{
    extern __shared__ char smem[];
    const uint32_t smem_base = smem_u32(smem);
    const int tid  = threadIdx.x;
    const int wid  = tid >> 5;
    const int lane = tid & 31;
    const int wm   = wid >> 2;   // 0..1
    const int wn   = wid & 3;    // 0..3

    const int m0  = blockIdx.x * BM;
    const int n0  = blockIdx.y * BN;
    const int rel = blockIdx.z;

    const __half* A = g_h16;
    const __half* B = g_wt16 + (size_t)rel * OUT_FEAT * IN_FEAT;

    float acc[4][4][4];
    #pragma unroll
    for (int i = 0; i < 4; i++)
        #pragma unroll
        for (int j = 0; j < 4; j++)
            #pragma unroll
            for (int k = 0; k < 4; k++)
                acc[i][j][k] = 0.0f;

    // ldmatrix address patterns (non-trans x4)
    const uint32_t aoff = (uint32_t)((wm * 64 + (lane & 15)) * A_STRIDE + (lane >> 4) * 16);
    const uint32_t boff = (uint32_t)((wn * 32 + ((lane >> 4) << 3) + (lane & 7)) * A_STRIDE +
                                     ((lane >> 3) & 1) * 16);

    const uint32_t sb[2] = { smem_base, smem_base + BUF_BYTES };

    load_chunk(sb[0], m0, n0, 0, tid, A, B);
    CP_COMMIT();

    for (int c = 0; c < NCHUNK; c++) {
        if (c + 1 < NCHUNK) {
            load_chunk(sb[(c + 1) & 1], m0, n0, (c + 1) * BKC, tid, A, B);
            CP_COMMIT();
            CP_WAIT(1);
        } else {
            CP_WAIT(0);
        }
        __syncthreads();

        const uint32_t buf = sb[c & 1];
        #pragma unroll
        for (int s = 0; s < 2; s++) {          // two k16 steps per 32-chunk
            uint32_t Af[4][4], Bf[2][4];
            #pragma unroll
            for (int mi = 0; mi < 4; mi++) {
                uint32_t ad = buf + aoff + (uint32_t)(mi * 16 * A_STRIDE + s * 32);
                LDSM_X4(Af[mi], ad + OFF_A);
            }
            #pragma unroll
            for (int nj = 0; nj < 2; nj++) {
                uint32_t bd = buf + boff + (uint32_t)(nj * 16 * A_STRIDE + s * 32);
                LDSM_X4(Bf[nj], bd + OFF_B);
            }
            #pragma unroll
            for (int mi = 0; mi < 4; mi++) {
                #pragma unroll
                for (int nf = 0; nf < 4; nf++) {
                    const int nj = nf >> 1, p = (nf & 1) * 2;
                    MMA_F16(acc[mi][nf], Af[mi], Bf[nj][p], Bf[nj][p + 1]);
                }
            }
        }
        __syncthreads();
    }

    // Epilogue: fp32 acc -> fp16 T.  c0,c1 at (row g, col tg*2), c2,c3 at row g+8.
    const int g  = lane >> 2;
    const int tg = lane & 3;
    __half* C = g_T + (size_t)rel * N_NODES * OUT_FEAT;
    #pragma unroll
    for (int mi = 0; mi < 4; mi++) {
        const int row0 = m0 + wm * 64 + mi * 16 + g;
        #pragma unroll
        for (int nf = 0; nf < 4; nf++) {
            const int col = n0 + wn * 32 + nf * 8 + tg * 2;
            if (row0 < N_NODES)
                *(__half2*)(C + (size_t)row0 * OUT_FEAT + col) =
                    __floats2half2_rn(acc[mi][nf][0], acc[mi][nf][1]);
            if (row0 + 8 < N_NODES)
                *(__half2*)(C + (size_t)(row0 + 8) * OUT_FEAT + col) =
                    __floats2half2_rn(acc[mi][nf][2], acc[mi][nf][3]);
        }
    }
}

// ---------------------------------------------------------------------------
// Kernel D: atomic-free gather over fp16 T.  64 threads per dst node
// (4 outputs each), 4 nodes per 256-thread block.
// ---------------------------------------------------------------------------
__global__ __launch_bounds__(256)
void rgcn_gather_kernel(float* __restrict__ out)
{
    const int node = blockIdx.x * 4 + (threadIdx.x >> 6);
    const int lane = threadIdx.x & 63;
    if (node >= N_NODES) return;

    const int beg = g_row[node];
    const int end = g_row[node + 1];

    float4 acc = make_float4(0.f, 0.f, 0.f, 0.f);
    int i = beg;
    for (; i + 1 < end; i += 2) {
        int2 e0 = g_es[i];
        int2 e1 = g_es[i + 1];
        int   s0 = e0.x & 0xFFFF, r0 = e0.x >> 16;
        int   s1 = e1.x & 0xFFFF, r1 = e1.x >> 16;
        float n0 = __int_as_float(e0.y);
        float n1 = __int_as_float(e1.y);
        uint2 u0 = ((const uint2*)(g_T + ((size_t)r0 * N_NODES + s0) * OUT_FEAT))[lane];
        uint2 u1 = ((const uint2*)(g_T + ((size_t)r1 * N_NODES + s1) * OUT_FEAT))[lane];
        float2 a0 = __half22float2(*(__half2*)&u0.x);
        float2 b0 = __half22float2(*(__half2*)&u0.y);
        float2 a1 = __half22float2(*(__half2*)&u1.x);
        float2 b1 = __half22float2(*(__half2*)&u1.y);
        acc.x = fmaf(a0.x, n0, acc.x); acc.y = fmaf(a0.y, n0, acc.y);
        acc.z = fmaf(b0.x, n0, acc.z); acc.w = fmaf(b0.y, n0, acc.w);
        acc.x = fmaf(a1.x, n1, acc.x); acc.y = fmaf(a1.y, n1, acc.y);
        acc.z = fmaf(b1.x, n1, acc.z); acc.w = fmaf(b1.y, n1, acc.w);
    }
    if (i < end) {
        int2 e0 = g_es[i];
        int   s0 = e0.x & 0xFFFF, r0 = e0.x >> 16;
        float n0 = __int_as_float(e0.y);
        uint2 u0 = ((const uint2*)(g_T + ((size_t)r0 * N_NODES + s0) * OUT_FEAT))[lane];
        float2 a0 = __half22float2(*(__half2*)&u0.x);
        float2 b0 = __half22float2(*(__half2*)&u0.y);
        acc.x = fmaf(a0.x, n0, acc.x); acc.y = fmaf(a0.y, n0, acc.y);
        acc.z = fmaf(b0.x, n0, acc.z); acc.w = fmaf(b0.y, n0, acc.w);
    }

    // lane covers cols [lane*4, lane*4+4)
    ((float4*)(out + (size_t)node * OUT_FEAT))[lane] = acc;
}

// ---------------------------------------------------------------------------
// Launch
// ---------------------------------------------------------------------------
extern "C" void kernel_launch(void* const* d_in, const int* in_sizes, int n_in,
                              void* d_out, int out_size)
{
    const float* h        = (const float*)d_in[0];
    const float* weight   = (const float*)d_in[1];
    const float* norm     = (const float*)d_in[2];
    const int*   src      = (const int*)d_in[3];
    const int*   dst      = (const int*)d_in[4];
    const int*   rel_type = (const int*)d_in[5];
    float*       out      = (float*)d_out;

    const int E = in_sizes[2];  // 320000

    conv_h_kernel<<<(N_NODES * IN_FEAT + 255) / 256, 256>>>(h);
    conv_wt_kernel<<<dim3(8, 8, NUM_RELS), dim3(32, 32)>>>(weight);

    csr_zero_kernel<<<(N_NODES + 255) / 256, 256>>>();
    csr_hist_kernel<<<(E + 255) / 256, 256>>>(dst, E);
    csr_scan_kernel<<<1, 256>>>();
    csr_fill_kernel<<<(E + 255) / 256, 256>>>(src, dst, rel_type, norm, E);

    cudaFuncSetAttribute(rgcn_gemm_hmma_kernel,
                         cudaFuncAttributeMaxDynamicSharedMemorySize, SM_TOTAL);
    rgcn_gemm_hmma_kernel<<<dim3(M_TILES, OUT_FEAT / BN, NUM_RELS), 256, SM_TOTAL>>>();

    rgcn_gather_kernel<<<(N_NODES + 3) / 4, 256>>>(out);
}

// round 9
// speedup vs baseline: 1.9080x; 1.0654x over previous
#include <cuda_runtime.h>
#include <cuda_fp16.h>
#include <cstdint>

// ---------------------------------------------------------------------------
// Problem constants
// ---------------------------------------------------------------------------
#define N_NODES  20000
#define N_EDGES  320000
#define NUM_RELS 16
#define IN_FEAT  256
#define OUT_FEAT 256

// ---------------------------------------------------------------------------
// Device scratch (static globals: allocation-guard safe)
// ---------------------------------------------------------------------------
__device__ __align__(16) __half g_T[(size_t)NUM_RELS * N_NODES * OUT_FEAT];   // 164 MB
__device__ __align__(16) __half g_h16[(size_t)N_NODES * IN_FEAT];             // 10 MB
__device__ __align__(16) __half g_wt16[(size_t)NUM_RELS * OUT_FEAT * IN_FEAT]; // [r][n][k], 2 MB

// CSR-by-dst scratch
__device__ int  g_cnt[N_NODES];
__device__ int  g_fill[N_NODES];
__device__ int  g_row[N_NODES + 1];
__device__ int2 g_es[N_EDGES];   // {src | (rel<<16), bitcast(norm)} sorted by dst

// ---------------------------------------------------------------------------
// PTX helpers (arch-agnostic: ldmatrix / mma.sync / cp.async only)
// ---------------------------------------------------------------------------
__device__ __forceinline__ uint32_t smem_u32(const void* p) {
    uint32_t a;
    asm("{ .reg .u64 t; cvta.to.shared.u64 t, %1; cvt.u32.u64 %0, t; }" : "=r"(a) : "l"(p));
    return a;
}

#define LDSM_X4(r, addr) \
    asm volatile("ldmatrix.sync.aligned.m8n8.x4.shared.b16 {%0,%1,%2,%3}, [%4];" \
        : "=r"((r)[0]), "=r"((r)[1]), "=r"((r)[2]), "=r"((r)[3]) : "r"(addr))

#define MMA_F16(d, a, b0, b1) \
    asm volatile("mma.sync.aligned.m16n8k16.row.col.f32.f16.f16.f32 " \
        "{%0,%1,%2,%3}, {%4,%5,%6,%7}, {%8,%9}, {%0,%1,%2,%3};" \
        : "+f"((d)[0]), "+f"((d)[1]), "+f"((d)[2]), "+f"((d)[3]) \
        : "r"((a)[0]), "r"((a)[1]), "r"((a)[2]), "r"((a)[3]), "r"(b0), "r"(b1))

#define CP_ASYNC16(saddr, gptr, nbytes) \
    asm volatile("cp.async.cg.shared.global [%0], [%1], 16, %2;" \
        :: "r"(saddr), "l"(gptr), "r"(nbytes))
#define CP_COMMIT() asm volatile("cp.async.commit_group;" ::: "memory")
#define CP_WAIT(n)  asm volatile("cp.async.wait_group %0;" :: "n"(n) : "memory")

// ---------------------------------------------------------------------------
// Kernel A: convert h to fp16
// ---------------------------------------------------------------------------
__global__ void conv_h_kernel(const float* __restrict__ h)
{
    int i = blockIdx.x * 256 + threadIdx.x;
    if (i < N_NODES * IN_FEAT)
        g_h16[i] = __float2half_rn(h[i]);
}

// ---------------------------------------------------------------------------
// Kernel B: transpose + convert W:  Wt[r][n][k] = W[r][k][n], fp16
// ---------------------------------------------------------------------------
__global__ void conv_wt_kernel(const float* __restrict__ W)
{
    __shared__ float tile[32][33];
    int r  = blockIdx.z;
    int k0 = blockIdx.x * 32;
    int n0 = blockIdx.y * 32;
    tile[threadIdx.y][threadIdx.x] =
        W[(size_t)r * 65536 + (size_t)(k0 + threadIdx.y) * 256 + n0 + threadIdx.x];
    __syncthreads();
    float x = tile[threadIdx.x][threadIdx.y];   // = W[r][k0+tx][n0+ty]
    size_t oi = (size_t)r * 65536 + (size_t)(n0 + threadIdx.y) * 256 + k0 + threadIdx.x;
    g_wt16[oi] = __float2half_rn(x);
}

// ---------------------------------------------------------------------------
// CSR build kernels
// ---------------------------------------------------------------------------
__global__ void csr_zero_kernel()
{
    int i = blockIdx.x * 256 + threadIdx.x;
    if (i < N_NODES) { g_cnt[i] = 0; g_fill[i] = 0; }
}

__global__ void csr_hist_kernel(const int* __restrict__ dst, int E)
{
    int e = blockIdx.x * 256 + threadIdx.x;
    if (e < E) atomicAdd(&g_cnt[dst[e]], 1);
}

// Single-block exclusive scan of g_cnt -> g_row (plus total at g_row[N]).
__global__ void csr_scan_kernel()
{
    __shared__ int ssum[256];
    const int t  = threadIdx.x;
    const int CH = (N_NODES + 255) / 256;   // 79
    const int base = t * CH;

    int s = 0;
    for (int i = 0; i < CH; i++) {
        int idx = base + i;
        if (idx < N_NODES) s += g_cnt[idx];
    }
    ssum[t] = s;
    __syncthreads();
    for (int off = 1; off < 256; off <<= 1) {
        int v = (t >= off) ? ssum[t - off] : 0;
        __syncthreads();
        ssum[t] += v;
        __syncthreads();
    }
    int run = (t > 0) ? ssum[t - 1] : 0;
    for (int i = 0; i < CH; i++) {
        int idx = base + i;
        if (idx < N_NODES) { g_row[idx] = run; run += g_cnt[idx]; }
    }
    if (t == 255) g_row[N_NODES] = run;
}

__global__ void csr_fill_kernel(const int* __restrict__ src,
                                const int* __restrict__ dst,
                                const int* __restrict__ rel_type,
                                const float* __restrict__ norm, int E)
{
    int e = blockIdx.x * 256 + threadIdx.x;
    if (e < E) {
        int d = dst[e];
        int pos = g_row[d] + atomicAdd(&g_fill[d], 1);
        g_es[pos] = make_int2(src[e] | (rel_type[e] << 16), __float_as_int(norm[e]));
    }
}

// ---------------------------------------------------------------------------
// Kernel C: single-pass fp16 HMMA GEMM.  T[r] = h @ W[r], fp32 accum, fp16 out.
// CTA 128x128, 8 warps (2m x 4n), warp tile 64x32, mma.m16n8k16.
// 3-stage cp.async pipeline, BK=32 (8 chunks of K=256).  2 CTAs/SM.
// ---------------------------------------------------------------------------
#define BM 128
#define BN 128
#define BKC 32
#define NCHUNK (IN_FEAT / BKC)      // 8
#define A_STRIDE 80                 // 64B payload + 16B pad (conflict-free ldmatrix)
#define TILE_BYTES (128 * A_STRIDE) // 10240 per tile
#define OFF_A 0
#define OFF_B TILE_BYTES
#define BUF_BYTES (2 * TILE_BYTES)  // 20480
#define NSTAGE 3
#define SM_TOTAL (NSTAGE * BUF_BYTES)  // 61440

#define M_TILES ((N_NODES + BM - 1) / BM)   // 157

__device__ __forceinline__ void load_chunk(
    uint32_t sbuf, int m0, int n0, int k0, int tid,
    const __half* __restrict__ A, const __half* __restrict__ B)
{
    #pragma unroll
    for (int it = 0; it < 2; it++) {
        int seg = tid + it * 256;      // 0..511
        int row = seg >> 2;            // 0..127
        int q   = seg & 3;             // 0..3 (16B units)
        uint32_t so = (uint32_t)(row * A_STRIDE + q * 16);
        int grow = m0 + row;
        int okA  = (grow < N_NODES) ? 16 : 0;
        int garow = (grow < N_NODES) ? grow : 0;
        CP_ASYNC16(sbuf + OFF_A + so, A + (size_t)garow * IN_FEAT + k0 + q * 8, okA);
        CP_ASYNC16(sbuf + OFF_B + so, B + (size_t)(n0 + row) * IN_FEAT + k0 + q * 8, 16);
    }
}

__global__ __launch_bounds__(256, 2)
void rgcn_gemm_hmma_kernel()
{
    extern __shared__ char smem[];
    const uint32_t smem_base = smem_u32(smem);
    const int tid  = threadIdx.x;
    const int wid  = tid >> 5;
    const int lane = tid & 31;
    const int wm   = wid >> 2;   // 0..1
    const int wn   = wid & 3;    // 0..3

    const int n0  = blockIdx.x * BN;
    const int m0  = blockIdx.y * BM;
    const int rel = blockIdx.z;

    const __half* A = g_h16;
    const __half* B = g_wt16 + (size_t)rel * OUT_FEAT * IN_FEAT;

    float acc[4][4][4];
    #pragma unroll
    for (int i = 0; i < 4; i++)
        #pragma unroll
        for (int j = 0; j < 4; j++)
            #pragma unroll
            for (int k = 0; k < 4; k++)
                acc[i][j][k] = 0.0f;

    const uint32_t aoff = (uint32_t)((wm * 64 + (lane & 15)) * A_STRIDE + (lane >> 4) * 16);
    const uint32_t boff = (uint32_t)((wn * 32 + ((lane >> 4) << 3) + (lane & 7)) * A_STRIDE +
                                     ((lane >> 3) & 1) * 16);

    const uint32_t sb[NSTAGE] = { smem_base, smem_base + BUF_BYTES, smem_base + 2 * BUF_BYTES };

    // Prologue: two chunks in flight.
    load_chunk(sb[0], m0, n0, 0, tid, A, B);
    CP_COMMIT();
    load_chunk(sb[1], m0, n0, BKC, tid, A, B);
    CP_COMMIT();

    int ld = 2;   // next chunk index to load
    for (int c = 0; c < NCHUNK; c++) {
        if (ld < NCHUNK)
            load_chunk(sb[ld % NSTAGE], m0, n0, ld * BKC, tid, A, B);
        ld++;
        CP_COMMIT();       // uniform group count (empty groups are legal)
        CP_WAIT(2);        // oldest outstanding (chunk c) complete
        __syncthreads();

        const uint32_t buf = sb[c % NSTAGE];
        #pragma unroll
        for (int s = 0; s < 2; s++) {          // two k16 steps per 32-chunk
            uint32_t Af[4][4], Bf[2][4];
            #pragma unroll
            for (int mi = 0; mi < 4; mi++) {
                uint32_t ad = buf + aoff + (uint32_t)(mi * 16 * A_STRIDE + s * 32);
                LDSM_X4(Af[mi], ad + OFF_A);
            }
            #pragma unroll
            for (int nj = 0; nj < 2; nj++) {
                uint32_t bd = buf + boff + (uint32_t)(nj * 16 * A_STRIDE + s * 32);
                LDSM_X4(Bf[nj], bd + OFF_B);
            }
            #pragma unroll
            for (int mi = 0; mi < 4; mi++) {
                #pragma unroll
                for (int nf = 0; nf < 4; nf++) {
                    const int nj = nf >> 1, p = (nf & 1) * 2;
                    MMA_F16(acc[mi][nf], Af[mi], Bf[nj][p], Bf[nj][p + 1]);
                }
            }
        }
        __syncthreads();
    }

    // Epilogue: fp32 acc -> fp16 T.
    const int g  = lane >> 2;
    const int tg = lane & 3;
    __half* C = g_T + (size_t)rel * N_NODES * OUT_FEAT;
    #pragma unroll
    for (int mi = 0; mi < 4; mi++) {
        const int row0 = m0 + wm * 64 + mi * 16 + g;
        #pragma unroll
        for (int nf = 0; nf < 4; nf++) {
            const int col = n0 + wn * 32 + nf * 8 + tg * 2;
            if (row0 < N_NODES)
                *(__half2*)(C + (size_t)row0 * OUT_FEAT + col) =
                    __floats2half2_rn(acc[mi][nf][0], acc[mi][nf][1]);
            if (row0 + 8 < N_NODES)
                *(__half2*)(C + (size_t)(row0 + 8) * OUT_FEAT + col) =
                    __floats2half2_rn(acc[mi][nf][2], acc[mi][nf][3]);
        }
    }
}

// ---------------------------------------------------------------------------
// Kernel D: atomic-free gather over fp16 T.  64 threads per dst node,
// 4-deep MLP unroll.
// ---------------------------------------------------------------------------
__device__ __forceinline__ void gacc(float4& acc, const uint2& u, float n)
{
    float2 a = __half22float2(*(const __half2*)&u.x);
    float2 b = __half22float2(*(const __half2*)&u.y);
    acc.x = fmaf(a.x, n, acc.x); acc.y = fmaf(a.y, n, acc.y);
    acc.z = fmaf(b.x, n, acc.z); acc.w = fmaf(b.y, n, acc.w);
}

__global__ __launch_bounds__(256)
void rgcn_gather_kernel(float* __restrict__ out)
{
    const int node = blockIdx.x * 4 + (threadIdx.x >> 6);
    const int lane = threadIdx.x & 63;
    if (node >= N_NODES) return;

    const int beg = g_row[node];
    const int end = g_row[node + 1];

    float4 acc = make_float4(0.f, 0.f, 0.f, 0.f);
    int i = beg;
    for (; i + 3 < end; i += 4) {
        int2 e0 = g_es[i], e1 = g_es[i + 1], e2 = g_es[i + 2], e3 = g_es[i + 3];
        const uint2 u0 = ((const uint2*)(g_T + ((size_t)(e0.x >> 16) * N_NODES + (e0.x & 0xFFFF)) * OUT_FEAT))[lane];
        const uint2 u1 = ((const uint2*)(g_T + ((size_t)(e1.x >> 16) * N_NODES + (e1.x & 0xFFFF)) * OUT_FEAT))[lane];
        const uint2 u2 = ((const uint2*)(g_T + ((size_t)(e2.x >> 16) * N_NODES + (e2.x & 0xFFFF)) * OUT_FEAT))[lane];
        const uint2 u3 = ((const uint2*)(g_T + ((size_t)(e3.x >> 16) * N_NODES + (e3.x & 0xFFFF)) * OUT_FEAT))[lane];
        gacc(acc, u0, __int_as_float(e0.y));
        gacc(acc, u1, __int_as_float(e1.y));
        gacc(acc, u2, __int_as_float(e2.y));
        gacc(acc, u3, __int_as_float(e3.y));
    }
    for (; i < end; i++) {
        int2 e0 = g_es[i];
        const uint2 u0 = ((const uint2*)(g_T + ((size_t)(e0.x >> 16) * N_NODES + (e0.x & 0xFFFF)) * OUT_FEAT))[lane];
        gacc(acc, u0, __int_as_float(e0.y));
    }

    ((float4*)(out + (size_t)node * OUT_FEAT))[lane] = acc;
}

// ---------------------------------------------------------------------------
// Launch
// ---------------------------------------------------------------------------
extern "C" void kernel_launch(void* const* d_in, const int* in_sizes, int n_in,
                              void* d_out, int out_size)
{
    const float* h        = (const float*)d_in[0];
    const float* weight   = (const float*)d_in[1];
    const float* norm     = (const float*)d_in[2];
    const int*   src      = (const int*)d_in[3];
    const int*   dst      = (const int*)d_in[4];
    const int*   rel_type = (const int*)d_in[5];
    float*       out      = (float*)d_out;

    const int E = in_sizes[2];  // 320000

    conv_h_kernel<<<(N_NODES * IN_FEAT + 255) / 256, 256>>>(h);
    conv_wt_kernel<<<dim3(8, 8, NUM_RELS), dim3(32, 32)>>>(weight);

    csr_zero_kernel<<<(N_NODES + 255) / 256, 256>>>();
    csr_hist_kernel<<<(E + 255) / 256, 256>>>(dst, E);
    csr_scan_kernel<<<1, 256>>>();
    csr_fill_kernel<<<(E + 255) / 256, 256>>>(src, dst, rel_type, norm, E);

    cudaFuncSetAttribute(rgcn_gemm_hmma_kernel,
                         cudaFuncAttributeMaxDynamicSharedMemorySize, SM_TOTAL);
    rgcn_gemm_hmma_kernel<<<dim3(OUT_FEAT / BN, M_TILES, NUM_RELS), 256, SM_TOTAL>>>();

    rgcn_gather_kernel<<<(N_NODES + 3) / 4, 256>>>(out);
}

// round 12
// speedup vs baseline: 2.2479x; 1.1782x over previous
#include <cuda_runtime.h>
#include <cuda_fp16.h>
#include <cstdint>

// ---------------------------------------------------------------------------
// Problem constants
// ---------------------------------------------------------------------------
#define N_NODES  20000
#define N_EDGES  320000
#define NUM_RELS 16
#define IN_FEAT  256
#define OUT_FEAT 256

// ---------------------------------------------------------------------------
// Device scratch (static globals: allocation-guard safe)
// ---------------------------------------------------------------------------
__device__ __align__(16) __half g_T[(size_t)NUM_RELS * N_NODES * OUT_FEAT];   // 164 MB
__device__ __align__(16) __half g_h16[(size_t)N_NODES * IN_FEAT];             // 10 MB
__device__ __align__(16) __half g_wt16[(size_t)NUM_RELS * OUT_FEAT * IN_FEAT]; // [r][n][k], 2 MB

// CSR-by-dst scratch
__device__ int  g_cnt[N_NODES];
__device__ int  g_fill[N_NODES];
__device__ int  g_row[N_NODES + 1];
__device__ int2 g_es[N_EDGES];   // {src | (rel<<16), bitcast(norm)} sorted by dst

// (rel, src) usage compaction
__device__ unsigned char g_used[NUM_RELS * N_NODES];  // 320 KB
__device__ int g_rcnt[NUM_RELS];
__device__ int g_list[NUM_RELS * N_NODES];            // per-rel used-src lists

// ---------------------------------------------------------------------------
// PTX helpers (arch-agnostic: ldmatrix / mma.sync / cp.async only)
// ---------------------------------------------------------------------------
__device__ __forceinline__ uint32_t smem_u32(const void* p) {
    uint32_t a;
    asm("{ .reg .u64 t; cvta.to.shared.u64 t, %1; cvt.u32.u64 %0, t; }" : "=r"(a) : "l"(p));
    return a;
}

#define LDSM_X4(r, addr) \
    asm volatile("ldmatrix.sync.aligned.m8n8.x4.shared.b16 {%0,%1,%2,%3}, [%4];" \
        : "=r"((r)[0]), "=r"((r)[1]), "=r"((r)[2]), "=r"((r)[3]) : "r"(addr))

#define MMA_F16(d, a, b0, b1) \
    asm volatile("mma.sync.aligned.m16n8k16.row.col.f32.f16.f16.f32 " \
        "{%0,%1,%2,%3}, {%4,%5,%6,%7}, {%8,%9}, {%0,%1,%2,%3};" \
        : "+f"((d)[0]), "+f"((d)[1]), "+f"((d)[2]), "+f"((d)[3]) \
        : "r"((a)[0]), "r"((a)[1]), "r"((a)[2]), "r"((a)[3]), "r"(b0), "r"(b1))

#define CP_ASYNC16(saddr, gptr, nbytes) \
    asm volatile("cp.async.cg.shared.global [%0], [%1], 16, %2;" \
        :: "r"(saddr), "l"(gptr), "r"(nbytes))
#define CP_COMMIT() asm volatile("cp.async.commit_group;" ::: "memory")
#define CP_WAIT(n)  asm volatile("cp.async.wait_group %0;" :: "n"(n) : "memory")

// ---------------------------------------------------------------------------
// Kernel A: convert h to fp16
// ---------------------------------------------------------------------------
__global__ void conv_h_kernel(const float* __restrict__ h)
{
    int i = blockIdx.x * 256 + threadIdx.x;
    if (i < N_NODES * IN_FEAT)
        g_h16[i] = __float2half_rn(h[i]);
}

// ---------------------------------------------------------------------------
// Kernel B: transpose + convert W:  Wt[r][n][k] = W[r][k][n], fp16
// ---------------------------------------------------------------------------
__global__ void conv_wt_kernel(const float* __restrict__ W)
{
    __shared__ float tile[32][33];
    int r  = blockIdx.z;
    int k0 = blockIdx.x * 32;
    int n0 = blockIdx.y * 32;
    tile[threadIdx.y][threadIdx.x] =
        W[(size_t)r * 65536 + (size_t)(k0 + threadIdx.y) * 256 + n0 + threadIdx.x];
    __syncthreads();
    float x = tile[threadIdx.x][threadIdx.y];   // = W[r][k0+tx][n0+ty]
    size_t oi = (size_t)r * 65536 + (size_t)(n0 + threadIdx.y) * 256 + k0 + threadIdx.x;
    g_wt16[oi] = __float2half_rn(x);
}

// ---------------------------------------------------------------------------
// Zero pass: counters + usage flags
// ---------------------------------------------------------------------------
__global__ void zero_kernel()
{
    int i = blockIdx.x * 256 + threadIdx.x;
    if (i < N_NODES) { g_cnt[i] = 0; g_fill[i] = 0; }
    if (i < NUM_RELS * N_NODES) g_used[i] = 0;
    if (i < NUM_RELS) g_rcnt[i] = 0;
}

// ---------------------------------------------------------------------------
// Mark pass (fused): dst histogram + (rel,src) usage flags
// ---------------------------------------------------------------------------
__global__ void mark_kernel(const int* __restrict__ src,
                            const int* __restrict__ dst,
                            const int* __restrict__ rel_type, int E)
{
    int e = blockIdx.x * 256 + threadIdx.x;
    if (e < E) {
        atomicAdd(&g_cnt[dst[e]], 1);
        g_used[rel_type[e] * N_NODES + src[e]] = 1;   // benign write race
    }
}

// ---------------------------------------------------------------------------
// Compact pass: per-rel used-src lists (warp-aggregated atomic append).
// N_NODES % 32 == 0 so each warp stays within one rel.
// ---------------------------------------------------------------------------
__global__ void compact_kernel()
{
    int i = blockIdx.x * 256 + threadIdx.x;   // 0 .. 16*20000-1
    if (i >= NUM_RELS * N_NODES) return;
    int r = i / N_NODES;
    int s = i - r * N_NODES;
    int lane = threadIdx.x & 31;

    bool u = (g_used[i] != 0);
    unsigned mask = __ballot_sync(0xFFFFFFFFu, u);
    if (mask == 0) return;
    int leader = __ffs(mask) - 1;
    int base = 0;
    if (lane == leader)
        base = atomicAdd(&g_rcnt[r], __popc(mask));
    base = __shfl_sync(0xFFFFFFFFu, base, leader);
    if (u) {
        int off = __popc(mask & ((1u << lane) - 1));
        g_list[r * N_NODES + base + off] = s;
    }
}

// ---------------------------------------------------------------------------
// Single-block exclusive scan of g_cnt -> g_row (plus total at g_row[N]).
// ---------------------------------------------------------------------------
__global__ void csr_scan_kernel()
{
    __shared__ int ssum[256];
    const int t  = threadIdx.x;
    const int CH = (N_NODES + 255) / 256;   // 79
    const int base = t * CH;

    int s = 0;
    for (int i = 0; i < CH; i++) {
        int idx = base + i;
        if (idx < N_NODES) s += g_cnt[idx];
    }
    ssum[t] = s;
    __syncthreads();
    for (int off = 1; off < 256; off <<= 1) {
        int v = (t >= off) ? ssum[t - off] : 0;
        __syncthreads();
        ssum[t] += v;
        __syncthreads();
    }
    int run = (t > 0) ? ssum[t - 1] : 0;
    for (int i = 0; i < CH; i++) {
        int idx = base + i;
        if (idx < N_NODES) { g_row[idx] = run; run += g_cnt[idx]; }
    }
    if (t == 255) g_row[N_NODES] = run;
}

__global__ void csr_fill_kernel(const int* __restrict__ src,
                                const int* __restrict__ dst,
                                const int* __restrict__ rel_type,
                                const float* __restrict__ norm, int E)
{
    int e = blockIdx.x * 256 + threadIdx.x;
    if (e < E) {
        int d = dst[e];
        int pos = g_row[d] + atomicAdd(&g_fill[d], 1);
        g_es[pos] = make_int2(src[e] | (rel_type[e] << 16), __float_as_int(norm[e]));
    }
}

// ---------------------------------------------------------------------------
// Kernel C: fp16 HMMA GEMM over COMPACTED rows.
// For rel r, rows = g_list[r][0..cnt): T[r][row] = h16[row] @ Wt[r]^T.
// CTA 128x128, 8 warps (2m x 4n), 3-stage cp.async pipeline, 2 CTAs/SM.
// ---------------------------------------------------------------------------
#define BM 128
#define BN 128
#define BKC 32
#define NCHUNK (IN_FEAT / BKC)      // 8
#define A_STRIDE 80                 // 64B payload + 16B pad (conflict-free ldmatrix)
#define TILE_BYTES (128 * A_STRIDE) // 10240 per tile
#define OFF_A 0
#define OFF_B TILE_BYTES
#define BUF_BYTES (2 * TILE_BYTES)  // 20480
#define NSTAGE 3
#define SM_TOTAL (NSTAGE * BUF_BYTES)  // 61440

#define M_TILES ((N_NODES + BM - 1) / BM)   // 157 (upper bound; most CTAs early-exit)

__global__ __launch_bounds__(256, 2)
void rgcn_gemm_hmma_kernel()
{
    const int rel = blockIdx.z;
    const int m0  = blockIdx.y * BM;
    const int cnt = g_rcnt[rel];
    if (m0 >= cnt) return;

    extern __shared__ char smem[];
    __shared__ int srows[BM];
    const uint32_t smem_base = smem_u32(smem);
    const int tid  = threadIdx.x;
    const int wid  = tid >> 5;
    const int lane = tid & 31;
    const int wm   = wid >> 2;   // 0..1
    const int wn   = wid & 3;    // 0..3

    const int n0 = blockIdx.x * BN;

    if (tid < BM) {
        int li = m0 + tid;
        srows[tid] = (li < cnt) ? g_list[rel * N_NODES + li] : -1;
    }
    __syncthreads();

    const __half* A = g_h16;
    const __half* B = g_wt16 + (size_t)rel * OUT_FEAT * IN_FEAT;

    float acc[4][4][4];
    #pragma unroll
    for (int i = 0; i < 4; i++)
        #pragma unroll
        for (int j = 0; j < 4; j++)
            #pragma unroll
            for (int k = 0; k < 4; k++)
                acc[i][j][k] = 0.0f;

    const uint32_t aoff = (uint32_t)((wm * 64 + (lane & 15)) * A_STRIDE + (lane >> 4) * 16);
    const uint32_t boff = (uint32_t)((wn * 32 + ((lane >> 4) << 3) + (lane & 7)) * A_STRIDE +
                                     ((lane >> 3) & 1) * 16);

    const uint32_t sb[NSTAGE] = { smem_base, smem_base + BUF_BYTES, smem_base + 2 * BUF_BYTES };

    // Indirect-row chunk loader (lambda-free for ptx clarity)
    #define LOAD_CHUNK(sbuf, k0) do {                                            \
        _Pragma("unroll")                                                        \
        for (int it = 0; it < 2; it++) {                                         \
            int seg = tid + it * 256;                                            \
            int row = seg >> 2;                                                  \
            int q   = seg & 3;                                                   \
            uint32_t so = (uint32_t)(row * A_STRIDE + q * 16);                   \
            int sr  = srows[row];                                                \
            int okA = (sr >= 0) ? 16 : 0;                                        \
            int ar  = (sr >= 0) ? sr : 0;                                        \
            CP_ASYNC16((sbuf) + OFF_A + so, A + (size_t)ar * IN_FEAT + (k0) + q * 8, okA); \
            CP_ASYNC16((sbuf) + OFF_B + so, B + (size_t)(n0 + row) * IN_FEAT + (k0) + q * 8, 16); \
        }                                                                        \
    } while (0)

    LOAD_CHUNK(sb[0], 0);
    CP_COMMIT();
    LOAD_CHUNK(sb[1], BKC);
    CP_COMMIT();

    int ld = 2;
    for (int c = 0; c < NCHUNK; c++) {
        if (ld < NCHUNK)
            LOAD_CHUNK(sb[ld % NSTAGE], ld * BKC);
        ld++;
        CP_COMMIT();
        CP_WAIT(2);
        __syncthreads();

        const uint32_t buf = sb[c % NSTAGE];
        #pragma unroll
        for (int s = 0; s < 2; s++) {
            uint32_t Af[4][4], Bf[2][4];
            #pragma unroll
            for (int mi = 0; mi < 4; mi++) {
                uint32_t ad = buf + aoff + (uint32_t)(mi * 16 * A_STRIDE + s * 32);
                LDSM_X4(Af[mi], ad + OFF_A);
            }
            #pragma unroll
            for (int nj = 0; nj < 2; nj++) {
                uint32_t bd = buf + boff + (uint32_t)(nj * 16 * A_STRIDE + s * 32);
                LDSM_X4(Bf[nj], bd + OFF_B);
            }
            #pragma unroll
            for (int mi = 0; mi < 4; mi++) {
                #pragma unroll
                for (int nf = 0; nf < 4; nf++) {
                    const int nj = nf >> 1, p = (nf & 1) * 2;
                    MMA_F16(acc[mi][nf], Af[mi], Bf[nj][p], Bf[nj][p + 1]);
                }
            }
        }
        __syncthreads();
    }
    #undef LOAD_CHUNK

    // Epilogue: indirect store, fp32 acc -> fp16 T[rel][src].
    const int g  = lane >> 2;
    const int tg = lane & 3;
    __half* C = g_T + (size_t)rel * N_NODES * OUT_FEAT;
    #pragma unroll
    for (int mi = 0; mi < 4; mi++) {
        const int lr0 = wm * 64 + mi * 16 + g;
        const int sr0 = srows[lr0];
        const int sr1 = srows[lr0 + 8];
        #pragma unroll
        for (int nf = 0; nf < 4; nf++) {
            const int col = n0 + wn * 32 + nf * 8 + tg * 2;
            if (sr0 >= 0)
                *(__half2*)(C + (size_t)sr0 * OUT_FEAT + col) =
                    __floats2half2_rn(acc[mi][nf][0], acc[mi][nf][1]);
            if (sr1 >= 0)
                *(__half2*)(C + (size_t)sr1 * OUT_FEAT + col) =
                    __floats2half2_rn(acc[mi][nf][2], acc[mi][nf][3]);
        }
    }
}

// ---------------------------------------------------------------------------
// Kernel D: atomic-free gather over fp16 T.  64 threads per dst node,
// 4-deep MLP unroll.
// ---------------------------------------------------------------------------
__device__ __forceinline__ void gacc(float4& acc, const uint2& u, float n)
{
    float2 a = __half22float2(*(const __half2*)&u.x);
    float2 b = __half22float2(*(const __half2*)&u.y);
    acc.x = fmaf(a.x, n, acc.x); acc.y = fmaf(a.y, n, acc.y);
    acc.z = fmaf(b.x, n, acc.z); acc.w = fmaf(b.y, n, acc.w);
}

__global__ __launch_bounds__(256)
void rgcn_gather_kernel(float* __restrict__ out)
{
    const int node = blockIdx.x * 4 + (threadIdx.x >> 6);
    const int lane = threadIdx.x & 63;
    if (node >= N_NODES) return;

    const int beg = g_row[node];
    const int end = g_row[node + 1];

    float4 acc = make_float4(0.f, 0.f, 0.f, 0.f);
    int i = beg;
    for (; i + 3 < end; i += 4) {
        int2 e0 = g_es[i], e1 = g_es[i + 1], e2 = g_es[i + 2], e3 = g_es[i + 3];
        const uint2 u0 = ((const uint2*)(g_T + ((size_t)(e0.x >> 16) * N_NODES + (e0.x & 0xFFFF)) * OUT_FEAT))[lane];
        const uint2 u1 = ((const uint2*)(g_T + ((size_t)(e1.x >> 16) * N_NODES + (e1.x & 0xFFFF)) * OUT_FEAT))[lane];
        const uint2 u2 = ((const uint2*)(g_T + ((size_t)(e2.x >> 16) * N_NODES + (e2.x & 0xFFFF)) * OUT_FEAT))[lane];
        const uint2 u3 = ((const uint2*)(g_T + ((size_t)(e3.x >> 16) * N_NODES + (e3.x & 0xFFFF)) * OUT_FEAT))[lane];
        gacc(acc, u0, __int_as_float(e0.y));
        gacc(acc, u1, __int_as_float(e1.y));
        gacc(acc, u2, __int_as_float(e2.y));
        gacc(acc, u3, __int_as_float(e3.y));
    }
    for (; i < end; i++) {
        int2 e0 = g_es[i];
        const uint2 u0 = ((const uint2*)(g_T + ((size_t)(e0.x >> 16) * N_NODES + (e0.x & 0xFFFF)) * OUT_FEAT))[lane];
        gacc(acc, u0, __int_as_float(e0.y));
    }

    ((float4*)(out + (size_t)node * OUT_FEAT))[lane] = acc;
}

// ---------------------------------------------------------------------------
// Launch
// ---------------------------------------------------------------------------
extern "C" void kernel_launch(void* const* d_in, const int* in_sizes, int n_in,
                              void* d_out, int out_size)
{
    const float* h        = (const float*)d_in[0];
    const float* weight   = (const float*)d_in[1];
    const float* norm     = (const float*)d_in[2];
    const int*   src      = (const int*)d_in[3];
    const int*   dst      = (const int*)d_in[4];
    const int*   rel_type = (const int*)d_in[5];
    float*       out      = (float*)d_out;

    const int E = in_sizes[2];  // 320000

    conv_h_kernel<<<(N_NODES * IN_FEAT + 255) / 256, 256>>>(h);
    conv_wt_kernel<<<dim3(8, 8, NUM_RELS), dim3(32, 32)>>>(weight);

    zero_kernel<<<(NUM_RELS * N_NODES + 255) / 256, 256>>>();
    mark_kernel<<<(E + 255) / 256, 256>>>(src, dst, rel_type, E);
    compact_kernel<<<(NUM_RELS * N_NODES + 255) / 256, 256>>>();
    csr_scan_kernel<<<1, 256>>>();
    csr_fill_kernel<<<(E + 255) / 256, 256>>>(src, dst, rel_type, norm, E);

    cudaFuncSetAttribute(rgcn_gemm_hmma_kernel,
                         cudaFuncAttributeMaxDynamicSharedMemorySize, SM_TOTAL);
    rgcn_gemm_hmma_kernel<<<dim3(OUT_FEAT / BN, M_TILES, NUM_RELS), 256, SM_TOTAL>>>();

    rgcn_gather_kernel<<<(N_NODES + 3) / 4, 256>>>(out);
}

// round 13
// speedup vs baseline: 2.3792x; 1.0584x over previous
#include <cuda_runtime.h>
#include <cuda_fp16.h>
#include <cstdint>

// ---------------------------------------------------------------------------
// Problem constants
// ---------------------------------------------------------------------------
#define N_NODES  20000
#define N_EDGES  320000
#define NUM_RELS 16
#define IN_FEAT  256
#define OUT_FEAT 256

// ---------------------------------------------------------------------------
// Device scratch (static globals: allocation-guard safe)
// ---------------------------------------------------------------------------
__device__ __align__(16) __half g_T[(size_t)NUM_RELS * N_NODES * OUT_FEAT];   // 164 MB
__device__ __align__(16) __half g_h16[(size_t)N_NODES * IN_FEAT];             // 10 MB
__device__ __align__(16) __half g_wt16[(size_t)NUM_RELS * OUT_FEAT * IN_FEAT]; // [r][n][k], 2 MB

// CSR-by-dst scratch
__device__ int  g_cnt[N_NODES];
__device__ int  g_fill[N_NODES];
__device__ int  g_row[N_NODES + 1];
__device__ int2 g_es[N_EDGES];   // {src | (rel<<16), bitcast(norm)} sorted by dst

// (rel, src) usage compaction
__device__ unsigned char g_used[NUM_RELS * N_NODES];  // 320 KB
__device__ int g_rcnt[NUM_RELS];
__device__ int g_list[NUM_RELS * N_NODES];            // per-rel used-src lists

// ---------------------------------------------------------------------------
// PTX helpers (arch-agnostic: ldmatrix / mma.sync / cp.async only)
// ---------------------------------------------------------------------------
__device__ __forceinline__ uint32_t smem_u32(const void* p) {
    uint32_t a;
    asm("{ .reg .u64 t; cvta.to.shared.u64 t, %1; cvt.u32.u64 %0, t; }" : "=r"(a) : "l"(p));
    return a;
}

#define LDSM_X4(r, addr) \
    asm volatile("ldmatrix.sync.aligned.m8n8.x4.shared.b16 {%0,%1,%2,%3}, [%4];" \
        : "=r"((r)[0]), "=r"((r)[1]), "=r"((r)[2]), "=r"((r)[3]) : "r"(addr))

#define MMA_F16(d, a, b0, b1) \
    asm volatile("mma.sync.aligned.m16n8k16.row.col.f32.f16.f16.f32 " \
        "{%0,%1,%2,%3}, {%4,%5,%6,%7}, {%8,%9}, {%0,%1,%2,%3};" \
        : "+f"((d)[0]), "+f"((d)[1]), "+f"((d)[2]), "+f"((d)[3]) \
        : "r"((a)[0]), "r"((a)[1]), "r"((a)[2]), "r"((a)[3]), "r"(b0), "r"(b1))

#define CP_ASYNC16(saddr, gptr, nbytes) \
    asm volatile("cp.async.cg.shared.global [%0], [%1], 16, %2;" \
        :: "r"(saddr), "l"(gptr), "r"(nbytes))
#define CP_COMMIT() asm volatile("cp.async.commit_group;" ::: "memory")
#define CP_WAIT(n)  asm volatile("cp.async.wait_group %0;" :: "n"(n) : "memory")

// ---------------------------------------------------------------------------
// Kernel A: convert h to fp16
// ---------------------------------------------------------------------------
__global__ void conv_h_kernel(const float* __restrict__ h)
{
    int i = blockIdx.x * 256 + threadIdx.x;
    if (i < N_NODES * IN_FEAT)
        g_h16[i] = __float2half_rn(h[i]);
}

// ---------------------------------------------------------------------------
// Kernel B: transpose + convert W:  Wt[r][n][k] = W[r][k][n], fp16
// ---------------------------------------------------------------------------
__global__ void conv_wt_kernel(const float* __restrict__ W)
{
    __shared__ float tile[32][33];
    int r  = blockIdx.z;
    int k0 = blockIdx.x * 32;
    int n0 = blockIdx.y * 32;
    tile[threadIdx.y][threadIdx.x] =
        W[(size_t)r * 65536 + (size_t)(k0 + threadIdx.y) * 256 + n0 + threadIdx.x];
    __syncthreads();
    float x = tile[threadIdx.x][threadIdx.y];   // = W[r][k0+tx][n0+ty]
    size_t oi = (size_t)r * 65536 + (size_t)(n0 + threadIdx.y) * 256 + k0 + threadIdx.x;
    g_wt16[oi] = __float2half_rn(x);
}

// ---------------------------------------------------------------------------
// Zero pass: counters + usage flags
// ---------------------------------------------------------------------------
__global__ void zero_kernel()
{
    int i = blockIdx.x * 256 + threadIdx.x;
    if (i < N_NODES) { g_cnt[i] = 0; g_fill[i] = 0; }
    if (i < NUM_RELS * N_NODES) g_used[i] = 0;
    if (i < NUM_RELS) g_rcnt[i] = 0;
}

// ---------------------------------------------------------------------------
// Mark pass (fused): dst histogram + (rel,src) usage flags
// ---------------------------------------------------------------------------
__global__ void mark_kernel(const int* __restrict__ src,
                            const int* __restrict__ dst,
                            const int* __restrict__ rel_type, int E)
{
    int e = blockIdx.x * 256 + threadIdx.x;
    if (e < E) {
        atomicAdd(&g_cnt[dst[e]], 1);
        g_used[rel_type[e] * N_NODES + src[e]] = 1;   // benign write race
    }
}

// ---------------------------------------------------------------------------
// Compact pass: per-rel used-src lists (warp-aggregated atomic append).
// N_NODES % 32 == 0 so each warp stays within one rel.
// ---------------------------------------------------------------------------
__global__ void compact_kernel()
{
    int i = blockIdx.x * 256 + threadIdx.x;   // 0 .. 16*20000-1
    if (i >= NUM_RELS * N_NODES) return;
    int r = i / N_NODES;
    int s = i - r * N_NODES;
    int lane = threadIdx.x & 31;

    bool u = (g_used[i] != 0);
    unsigned mask = __ballot_sync(0xFFFFFFFFu, u);
    if (mask == 0) return;
    int leader = __ffs(mask) - 1;
    int base = 0;
    if (lane == leader)
        base = atomicAdd(&g_rcnt[r], __popc(mask));
    base = __shfl_sync(0xFFFFFFFFu, base, leader);
    if (u) {
        int off = __popc(mask & ((1u << lane) - 1));
        g_list[r * N_NODES + base + off] = s;
    }
}

// ---------------------------------------------------------------------------
// Single-block exclusive scan of g_cnt -> g_row (plus total at g_row[N]).
// ---------------------------------------------------------------------------
__global__ void csr_scan_kernel()
{
    __shared__ int ssum[256];
    const int t  = threadIdx.x;
    const int CH = (N_NODES + 255) / 256;   // 79
    const int base = t * CH;

    int s = 0;
    for (int i = 0; i < CH; i++) {
        int idx = base + i;
        if (idx < N_NODES) s += g_cnt[idx];
    }
    ssum[t] = s;
    __syncthreads();
    for (int off = 1; off < 256; off <<= 1) {
        int v = (t >= off) ? ssum[t - off] : 0;
        __syncthreads();
        ssum[t] += v;
        __syncthreads();
    }
    int run = (t > 0) ? ssum[t - 1] : 0;
    for (int i = 0; i < CH; i++) {
        int idx = base + i;
        if (idx < N_NODES) { g_row[idx] = run; run += g_cnt[idx]; }
    }
    if (t == 255) g_row[N_NODES] = run;
}

__global__ void csr_fill_kernel(const int* __restrict__ src,
                                const int* __restrict__ dst,
                                const int* __restrict__ rel_type,
                                const float* __restrict__ norm, int E)
{
    int e = blockIdx.x * 256 + threadIdx.x;
    if (e < E) {
        int d = dst[e];
        int pos = g_row[d] + atomicAdd(&g_fill[d], 1);
        g_es[pos] = make_int2(src[e] | (rel_type[e] << 16), __float_as_int(norm[e]));
    }
}

// ---------------------------------------------------------------------------
// Kernel C: fp16 HMMA GEMM over COMPACTED rows.
// CTA 128x128, 4 warps (2m x 2n), warp tile 64x64 (crossbar-balanced),
// 3-stage cp.async pipeline, __launch_bounds__(128, 2) -> 2 CTAs/SM.
// ---------------------------------------------------------------------------
#define BM 128
#define BN 128
#define BKC 32
#define NCHUNK (IN_FEAT / BKC)      // 8
#define A_STRIDE 80                 // 64B payload + 16B pad (conflict-free ldmatrix)
#define TILE_BYTES (128 * A_STRIDE) // 10240 per tile
#define OFF_A 0
#define OFF_B TILE_BYTES
#define BUF_BYTES (2 * TILE_BYTES)  // 20480
#define NSTAGE 3
#define SM_TOTAL (NSTAGE * BUF_BYTES)  // 61440
#define GEMM_THREADS 128

#define M_TILES ((N_NODES + BM - 1) / BM)   // 157 (upper bound; CTAs early-exit)

__global__ __launch_bounds__(GEMM_THREADS, 2)
void rgcn_gemm_hmma_kernel()
{
    const int rel = blockIdx.z;
    const int m0  = blockIdx.y * BM;
    const int cnt = g_rcnt[rel];
    if (m0 >= cnt) return;

    extern __shared__ char smem[];
    __shared__ int srows[BM];
    const uint32_t smem_base = smem_u32(smem);
    const int tid  = threadIdx.x;
    const int wid  = tid >> 5;
    const int lane = tid & 31;
    const int wm   = wid >> 1;   // 0..1
    const int wn   = wid & 1;    // 0..1

    const int n0 = blockIdx.x * BN;

    if (tid < BM) {
        int li = m0 + tid;
        srows[tid] = (li < cnt) ? g_list[rel * N_NODES + li] : -1;
    }
    __syncthreads();

    const __half* A = g_h16;
    const __half* B = g_wt16 + (size_t)rel * OUT_FEAT * IN_FEAT;

    float acc[4][8][4];   // mi x nf x frag = 128 regs
    #pragma unroll
    for (int i = 0; i < 4; i++)
        #pragma unroll
        for (int j = 0; j < 8; j++)
            #pragma unroll
            for (int k = 0; k < 4; k++)
                acc[i][j][k] = 0.0f;

    const uint32_t aoff = (uint32_t)((wm * 64 + (lane & 15)) * A_STRIDE + (lane >> 4) * 16);
    const uint32_t boff = (uint32_t)((wn * 64 + ((lane >> 4) << 3) + (lane & 7)) * A_STRIDE +
                                     ((lane >> 3) & 1) * 16);

    const uint32_t sb[NSTAGE] = { smem_base, smem_base + BUF_BYTES, smem_base + 2 * BUF_BYTES };

    // Indirect-row chunk loader: each tile = 512 x 16B segs, 128 threads -> 4 iters
    #define LOAD_CHUNK(sbuf, k0) do {                                            \
        _Pragma("unroll")                                                        \
        for (int it = 0; it < 4; it++) {                                         \
            int seg = tid + it * GEMM_THREADS;                                   \
            int row = seg >> 2;                                                  \
            int q   = seg & 3;                                                   \
            uint32_t so = (uint32_t)(row * A_STRIDE + q * 16);                   \
            int sr  = srows[row];                                                \
            int okA = (sr >= 0) ? 16 : 0;                                        \
            int ar  = (sr >= 0) ? sr : 0;                                        \
            CP_ASYNC16((sbuf) + OFF_A + so, A + (size_t)ar * IN_FEAT + (k0) + q * 8, okA); \
            CP_ASYNC16((sbuf) + OFF_B + so, B + (size_t)(n0 + row) * IN_FEAT + (k0) + q * 8, 16); \
        }                                                                        \
    } while (0)

    LOAD_CHUNK(sb[0], 0);
    CP_COMMIT();
    LOAD_CHUNK(sb[1], BKC);
    CP_COMMIT();

    int ld = 2;
    for (int c = 0; c < NCHUNK; c++) {
        if (ld < NCHUNK)
            LOAD_CHUNK(sb[ld % NSTAGE], ld * BKC);
        ld++;
        CP_COMMIT();
        CP_WAIT(2);
        __syncthreads();

        const uint32_t buf = sb[c % NSTAGE];
        #pragma unroll
        for (int s = 0; s < 2; s++) {          // two k16 steps per 32-chunk
            uint32_t Af[4][4], Bf[4][4];
            #pragma unroll
            for (int mi = 0; mi < 4; mi++) {
                uint32_t ad = buf + aoff + (uint32_t)(mi * 16 * A_STRIDE + s * 32);
                LDSM_X4(Af[mi], ad + OFF_A);
            }
            #pragma unroll
            for (int nj = 0; nj < 4; nj++) {
                uint32_t bd = buf + boff + (uint32_t)(nj * 16 * A_STRIDE + s * 32);
                LDSM_X4(Bf[nj], bd + OFF_B);
            }
            #pragma unroll
            for (int mi = 0; mi < 4; mi++) {
                #pragma unroll
                for (int nf = 0; nf < 8; nf++) {
                    const int nj = nf >> 1, p = (nf & 1) * 2;
                    MMA_F16(acc[mi][nf], Af[mi], Bf[nj][p], Bf[nj][p + 1]);
                }
            }
        }
        __syncthreads();
    }
    #undef LOAD_CHUNK

    // Epilogue: indirect store, fp32 acc -> fp16 T[rel][src].
    const int g  = lane >> 2;
    const int tg = lane & 3;
    __half* C = g_T + (size_t)rel * N_NODES * OUT_FEAT;
    #pragma unroll
    for (int mi = 0; mi < 4; mi++) {
        const int lr0 = wm * 64 + mi * 16 + g;
        const int sr0 = srows[lr0];
        const int sr1 = srows[lr0 + 8];
        #pragma unroll
        for (int nf = 0; nf < 8; nf++) {
            const int col = n0 + wn * 64 + nf * 8 + tg * 2;
            if (sr0 >= 0)
                *(__half2*)(C + (size_t)sr0 * OUT_FEAT + col) =
                    __floats2half2_rn(acc[mi][nf][0], acc[mi][nf][1]);
            if (sr1 >= 0)
                *(__half2*)(C + (size_t)sr1 * OUT_FEAT + col) =
                    __floats2half2_rn(acc[mi][nf][2], acc[mi][nf][3]);
        }
    }
}

// ---------------------------------------------------------------------------
// Kernel D: atomic-free gather over fp16 T.  64 threads per dst node,
// 4-deep MLP unroll.
// ---------------------------------------------------------------------------
__device__ __forceinline__ void gacc(float4& acc, const uint2& u, float n)
{
    float2 a = __half22float2(*(const __half2*)&u.x);
    float2 b = __half22float2(*(const __half2*)&u.y);
    acc.x = fmaf(a.x, n, acc.x); acc.y = fmaf(a.y, n, acc.y);
    acc.z = fmaf(b.x, n, acc.z); acc.w = fmaf(b.y, n, acc.w);
}

__global__ __launch_bounds__(256)
void rgcn_gather_kernel(float* __restrict__ out)
{
    const int node = blockIdx.x * 4 + (threadIdx.x >> 6);
    const int lane = threadIdx.x & 63;
    if (node >= N_NODES) return;

    const int beg = g_row[node];
    const int end = g_row[node + 1];

    float4 acc = make_float4(0.f, 0.f, 0.f, 0.f);
    int i = beg;
    for (; i + 3 < end; i += 4) {
        int2 e0 = g_es[i], e1 = g_es[i + 1], e2 = g_es[i + 2], e3 = g_es[i + 3];
        const uint2 u0 = ((const uint2*)(g_T + ((size_t)(e0.x >> 16) * N_NODES + (e0.x & 0xFFFF)) * OUT_FEAT))[lane];
        const uint2 u1 = ((const uint2*)(g_T + ((size_t)(e1.x >> 16) * N_NODES + (e1.x & 0xFFFF)) * OUT_FEAT))[lane];
        const uint2 u2 = ((const uint2*)(g_T + ((size_t)(e2.x >> 16) * N_NODES + (e2.x & 0xFFFF)) * OUT_FEAT))[lane];
        const uint2 u3 = ((const uint2*)(g_T + ((size_t)(e3.x >> 16) * N_NODES + (e3.x & 0xFFFF)) * OUT_FEAT))[lane];
        gacc(acc, u0, __int_as_float(e0.y));
        gacc(acc, u1, __int_as_float(e1.y));
        gacc(acc, u2, __int_as_float(e2.y));
        gacc(acc, u3, __int_as_float(e3.y));
    }
    for (; i < end; i++) {
        int2 e0 = g_es[i];
        const uint2 u0 = ((const uint2*)(g_T + ((size_t)(e0.x >> 16) * N_NODES + (e0.x & 0xFFFF)) * OUT_FEAT))[lane];
        gacc(acc, u0, __int_as_float(e0.y));
    }

    ((float4*)(out + (size_t)node * OUT_FEAT))[lane] = acc;
}

// ---------------------------------------------------------------------------
// Launch
// ---------------------------------------------------------------------------
extern "C" void kernel_launch(void* const* d_in, const int* in_sizes, int n_in,
                              void* d_out, int out_size)
{
    const float* h        = (const float*)d_in[0];
    const float* weight   = (const float*)d_in[1];
    const float* norm     = (const float*)d_in[2];
    const int*   src      = (const int*)d_in[3];
    const int*   dst      = (const int*)d_in[4];
    const int*   rel_type = (const int*)d_in[5];
    float*       out      = (float*)d_out;

    const int E = in_sizes[2];  // 320000

    conv_h_kernel<<<(N_NODES * IN_FEAT + 255) / 256, 256>>>(h);
    conv_wt_kernel<<<dim3(8, 8, NUM_RELS), dim3(32, 32)>>>(weight);

    zero_kernel<<<(NUM_RELS * N_NODES + 255) / 256, 256>>>();
    mark_kernel<<<(E + 255) / 256, 256>>>(src, dst, rel_type, E);
    compact_kernel<<<(NUM_RELS * N_NODES + 255) / 256, 256>>>();
    csr_scan_kernel<<<1, 256>>>();
    csr_fill_kernel<<<(E + 255) / 256, 256>>>(src, dst, rel_type, norm, E);

    cudaFuncSetAttribute(rgcn_gemm_hmma_kernel,
                         cudaFuncAttributeMaxDynamicSharedMemorySize, SM_TOTAL);
    rgcn_gemm_hmma_kernel<<<dim3(OUT_FEAT / BN, M_TILES, NUM_RELS), GEMM_THREADS, SM_TOTAL>>>();

    rgcn_gather_kernel<<<(N_NODES + 3) / 4, 256>>>(out);
}

// round 14
// speedup vs baseline: 2.5605x; 1.0762x over previous
#include <cuda_runtime.h>
#include <cuda_fp16.h>
#include <cstdint>

// ---------------------------------------------------------------------------
// Problem constants
// ---------------------------------------------------------------------------
#define N_NODES  20000
#define N_EDGES  320000
#define NUM_RELS 16
#define IN_FEAT  256
#define OUT_FEAT 256
#define USED_WORDS (NUM_RELS * N_NODES / 32)   // 10000
#define WORDS_PER_REL (N_NODES / 32)           // 625

// ---------------------------------------------------------------------------
// Device scratch (static globals: allocation-guard safe)
// ---------------------------------------------------------------------------
__device__ __align__(16) __half g_T[(size_t)NUM_RELS * N_NODES * OUT_FEAT];   // 164 MB
__device__ __align__(16) __half g_h16[(size_t)N_NODES * IN_FEAT];             // 10 MB
__device__ __align__(16) __half g_wt16[(size_t)NUM_RELS * OUT_FEAT * IN_FEAT]; // [r][n][k], 2 MB

// CSR-by-dst scratch
__device__ int  g_cnt[N_NODES];
__device__ int  g_fill[N_NODES];
__device__ int  g_row[N_NODES + 1];
__device__ int2 g_es[N_EDGES];   // {src | (rel<<16), bitcast(norm)} sorted by dst

// (rel, src) usage compaction (bitmask)
__device__ unsigned int g_usedw[USED_WORDS];   // 40 KB, L2-resident
__device__ int g_rcnt[NUM_RELS];
__device__ int g_list[NUM_RELS * N_NODES];     // per-rel used-src lists

// ---------------------------------------------------------------------------
// PTX helpers (arch-agnostic: ldmatrix / mma.sync / cp.async only)
// ---------------------------------------------------------------------------
__device__ __forceinline__ uint32_t smem_u32(const void* p) {
    uint32_t a;
    asm("{ .reg .u64 t; cvta.to.shared.u64 t, %1; cvt.u32.u64 %0, t; }" : "=r"(a) : "l"(p));
    return a;
}

#define LDSM_X4(r, addr) \
    asm volatile("ldmatrix.sync.aligned.m8n8.x4.shared.b16 {%0,%1,%2,%3}, [%4];" \
        : "=r"((r)[0]), "=r"((r)[1]), "=r"((r)[2]), "=r"((r)[3]) : "r"(addr))

#define MMA_F16(d, a, b0, b1) \
    asm volatile("mma.sync.aligned.m16n8k16.row.col.f32.f16.f16.f32 " \
        "{%0,%1,%2,%3}, {%4,%5,%6,%7}, {%8,%9}, {%0,%1,%2,%3};" \
        : "+f"((d)[0]), "+f"((d)[1]), "+f"((d)[2]), "+f"((d)[3]) \
        : "r"((a)[0]), "r"((a)[1]), "r"((a)[2]), "r"((a)[3]), "r"(b0), "r"(b1))

#define CP_ASYNC16(saddr, gptr, nbytes) \
    asm volatile("cp.async.cg.shared.global [%0], [%1], 16, %2;" \
        :: "r"(saddr), "l"(gptr), "r"(nbytes))
#define CP_COMMIT() asm volatile("cp.async.commit_group;" ::: "memory")
#define CP_WAIT(n)  asm volatile("cp.async.wait_group %0;" :: "n"(n) : "memory")

// ---------------------------------------------------------------------------
// Kernel A (fused): convert h to fp16 + zero all counters/flags
// ---------------------------------------------------------------------------
__global__ void conv_h_zero_kernel(const float* __restrict__ h)
{
    int i = blockIdx.x * 256 + threadIdx.x;
    if (i < N_NODES * IN_FEAT)
        g_h16[i] = __float2half_rn(h[i]);
    if (i < N_NODES) { g_cnt[i] = 0; g_fill[i] = 0; }
    if (i < USED_WORDS) g_usedw[i] = 0u;
    if (i < NUM_RELS) g_rcnt[i] = 0;
}

// ---------------------------------------------------------------------------
// Kernel B: transpose + convert W:  Wt[r][n][k] = W[r][k][n], fp16
// ---------------------------------------------------------------------------
__global__ void conv_wt_kernel(const float* __restrict__ W)
{
    __shared__ float tile[32][33];
    int r  = blockIdx.z;
    int k0 = blockIdx.x * 32;
    int n0 = blockIdx.y * 32;
    tile[threadIdx.y][threadIdx.x] =
        W[(size_t)r * 65536 + (size_t)(k0 + threadIdx.y) * 256 + n0 + threadIdx.x];
    __syncthreads();
    float x = tile[threadIdx.x][threadIdx.y];   // = W[r][k0+tx][n0+ty]
    size_t oi = (size_t)r * 65536 + (size_t)(n0 + threadIdx.y) * 256 + k0 + threadIdx.x;
    g_wt16[oi] = __float2half_rn(x);
}

// ---------------------------------------------------------------------------
// Mark pass (fused): dst histogram + (rel,src) usage bitmask
// ---------------------------------------------------------------------------
__global__ void mark_kernel(const int* __restrict__ src,
                            const int* __restrict__ dst,
                            const int* __restrict__ rel_type, int E)
{
    int e = blockIdx.x * 256 + threadIdx.x;
    if (e < E) {
        atomicAdd(&g_cnt[dst[e]], 1);
        int idx = rel_type[e] * N_NODES + src[e];
        atomicOr(&g_usedw[idx >> 5], 1u << (idx & 31));
    }
}

// ---------------------------------------------------------------------------
// Compact pass: per-rel used-src lists.  One warp per 32-bit usage word
// (the ballot mask IS the word).  WORDS_PER_REL=625 aligns warps to rels.
// ---------------------------------------------------------------------------
__global__ void compact_kernel()
{
    int w = blockIdx.x * 8 + (threadIdx.x >> 5);   // word index 0..9999
    if (w >= USED_WORDS) return;
    int lane = threadIdx.x & 31;
    int r = w / WORDS_PER_REL;
    int s = (w - r * WORDS_PER_REL) * 32 + lane;

    unsigned mask = g_usedw[w];                     // broadcast load
    if (mask == 0) return;
    int base = 0;
    if (lane == 0)
        base = atomicAdd(&g_rcnt[r], __popc(mask));
    base = __shfl_sync(0xFFFFFFFFu, base, 0);
    if (mask & (1u << lane)) {
        int off = __popc(mask & ((1u << lane) - 1));
        g_list[r * N_NODES + base + off] = s;
    }
}

// ---------------------------------------------------------------------------
// Single-block exclusive scan of g_cnt -> g_row (1024 threads, CH=20).
// ---------------------------------------------------------------------------
__global__ void csr_scan_kernel()
{
    __shared__ int ssum[1024];
    const int t  = threadIdx.x;
    const int CH = (N_NODES + 1023) / 1024;   // 20
    const int base = t * CH;

    int s = 0;
    for (int i = 0; i < CH; i++) {
        int idx = base + i;
        if (idx < N_NODES) s += g_cnt[idx];
    }
    ssum[t] = s;
    __syncthreads();
    for (int off = 1; off < 1024; off <<= 1) {
        int v = (t >= off) ? ssum[t - off] : 0;
        __syncthreads();
        ssum[t] += v;
        __syncthreads();
    }
    int run = (t > 0) ? ssum[t - 1] : 0;
    for (int i = 0; i < CH; i++) {
        int idx = base + i;
        if (idx < N_NODES) { g_row[idx] = run; run += g_cnt[idx]; }
    }
    if (t == 1023) g_row[N_NODES] = ssum[1023];
}

__global__ void csr_fill_kernel(const int* __restrict__ src,
                                const int* __restrict__ dst,
                                const int* __restrict__ rel_type,
                                const float* __restrict__ norm, int E)
{
    int e = blockIdx.x * 256 + threadIdx.x;
    if (e < E) {
        int d = dst[e];
        int pos = g_row[d] + atomicAdd(&g_fill[d], 1);
        g_es[pos] = make_int2(src[e] | (rel_type[e] << 16), __float_as_int(norm[e]));
    }
}

// ---------------------------------------------------------------------------
// Kernel C: fp16 HMMA GEMM over COMPACTED rows.
// CTA 128x128, 4 warps (2m x 2n), warp tile 64x64, 3-stage cp.async
// pipeline with ONE __syncthreads per chunk, 2 CTAs/SM.
// ---------------------------------------------------------------------------
#define BM 128
#define BN 128
#define BKC 32
#define NCHUNK (IN_FEAT / BKC)      // 8
#define A_STRIDE 80                 // 64B payload + 16B pad (conflict-free ldmatrix)
#define TILE_BYTES (128 * A_STRIDE) // 10240 per tile
#define OFF_A 0
#define OFF_B TILE_BYTES
#define BUF_BYTES (2 * TILE_BYTES)  // 20480
#define NSTAGE 3
#define SM_TOTAL (NSTAGE * BUF_BYTES)  // 61440
#define GEMM_THREADS 128

#define M_TILES ((N_NODES + BM - 1) / BM)   // 157 (upper bound; CTAs early-exit)

__global__ __launch_bounds__(GEMM_THREADS, 2)
void rgcn_gemm_hmma_kernel()
{
    const int rel = blockIdx.z;
    const int m0  = blockIdx.y * BM;
    const int cnt = g_rcnt[rel];
    if (m0 >= cnt) return;

    extern __shared__ char smem[];
    __shared__ int srows[BM];
    const uint32_t smem_base = smem_u32(smem);
    const int tid  = threadIdx.x;
    const int wid  = tid >> 5;
    const int lane = tid & 31;
    const int wm   = wid >> 1;   // 0..1
    const int wn   = wid & 1;    // 0..1

    const int n0 = blockIdx.x * BN;

    if (tid < BM) {
        int li = m0 + tid;
        srows[tid] = (li < cnt) ? g_list[rel * N_NODES + li] : -1;
    }
    __syncthreads();

    const __half* A = g_h16;
    const __half* B = g_wt16 + (size_t)rel * OUT_FEAT * IN_FEAT;

    float acc[4][8][4];   // mi x nf x frag = 128 regs
    #pragma unroll
    for (int i = 0; i < 4; i++)
        #pragma unroll
        for (int j = 0; j < 8; j++)
            #pragma unroll
            for (int k = 0; k < 4; k++)
                acc[i][j][k] = 0.0f;

    const uint32_t aoff = (uint32_t)((wm * 64 + (lane & 15)) * A_STRIDE + (lane >> 4) * 16);
    const uint32_t boff = (uint32_t)((wn * 64 + ((lane >> 4) << 3) + (lane & 7)) * A_STRIDE +
                                     ((lane >> 3) & 1) * 16);

    const uint32_t sb[NSTAGE] = { smem_base, smem_base + BUF_BYTES, smem_base + 2 * BUF_BYTES };

    // Indirect-row chunk loader: each tile = 512 x 16B segs, 128 threads -> 4 iters
    #define LOAD_CHUNK(sbuf, k0) do {                                            \
        _Pragma("unroll")                                                        \
        for (int it = 0; it < 4; it++) {                                         \
            int seg = tid + it * GEMM_THREADS;                                   \
            int row = seg >> 2;                                                  \
            int q   = seg & 3;                                                   \
            uint32_t so = (uint32_t)(row * A_STRIDE + q * 16);                   \
            int sr  = srows[row];                                                \
            int okA = (sr >= 0) ? 16 : 0;                                        \
            int ar  = (sr >= 0) ? sr : 0;                                        \
            CP_ASYNC16((sbuf) + OFF_A + so, A + (size_t)ar * IN_FEAT + (k0) + q * 8, okA); \
            CP_ASYNC16((sbuf) + OFF_B + so, B + (size_t)(n0 + row) * IN_FEAT + (k0) + q * 8, 16); \
        }                                                                        \
    } while (0)

    LOAD_CHUNK(sb[0], 0);
    CP_COMMIT();
    LOAD_CHUNK(sb[1], BKC);
    CP_COMMIT();

    for (int c = 0; c < NCHUNK; c++) {
        CP_WAIT(1);            // chunk c arrived (c+1 may still be in flight)
        __syncthreads();       // single barrier per chunk

        const uint32_t buf = sb[c % NSTAGE];
        #pragma unroll
        for (int s = 0; s < 2; s++) {          // two k16 steps per 32-chunk
            uint32_t Af[4][4], Bf[4][4];
            #pragma unroll
            for (int mi = 0; mi < 4; mi++) {
                uint32_t ad = buf + aoff + (uint32_t)(mi * 16 * A_STRIDE + s * 32);
                LDSM_X4(Af[mi], ad + OFF_A);
            }
            #pragma unroll
            for (int nj = 0; nj < 4; nj++) {
                uint32_t bd = buf + boff + (uint32_t)(nj * 16 * A_STRIDE + s * 32);
                LDSM_X4(Bf[nj], bd + OFF_B);
            }
            #pragma unroll
            for (int mi = 0; mi < 4; mi++) {
                #pragma unroll
                for (int nf = 0; nf < 8; nf++) {
                    const int nj = nf >> 1, p = (nf & 1) * 2;
                    MMA_F16(acc[mi][nf], Af[mi], Bf[nj][p], Bf[nj][p + 1]);
                }
            }
        }

        // Refill stage (c+2)%NSTAGE (== stage of chunk c-1; all warps passed
        // the barrier above after finishing chunk c-1's compute).
        if (c + 2 < NCHUNK)
            LOAD_CHUNK(sb[(c + 2) % NSTAGE], (c + 2) * BKC);
        CP_COMMIT();           // uniform group count (empty groups legal)
    }
    #undef LOAD_CHUNK

    // Epilogue: indirect store, fp32 acc -> fp16 T[rel][src].
    const int g  = lane >> 2;
    const int tg = lane & 3;
    __half* C = g_T + (size_t)rel * N_NODES * OUT_FEAT;
    #pragma unroll
    for (int mi = 0; mi < 4; mi++) {
        const int lr0 = wm * 64 + mi * 16 + g;
        const int sr0 = srows[lr0];
        const int sr1 = srows[lr0 + 8];
        #pragma unroll
        for (int nf = 0; nf < 8; nf++) {
            const int col = n0 + wn * 64 + nf * 8 + tg * 2;
            if (sr0 >= 0)
                *(__half2*)(C + (size_t)sr0 * OUT_FEAT + col) =
                    __floats2half2_rn(acc[mi][nf][0], acc[mi][nf][1]);
            if (sr1 >= 0)
                *(__half2*)(C + (size_t)sr1 * OUT_FEAT + col) =
                    __floats2half2_rn(acc[mi][nf][2], acc[mi][nf][3]);
        }
    }
}

// ---------------------------------------------------------------------------
// Kernel D: atomic-free gather over fp16 T.  64 threads per dst node,
// 4-deep MLP unroll.
// ---------------------------------------------------------------------------
__device__ __forceinline__ void gacc(float4& acc, const uint2& u, float n)
{
    float2 a = __half22float2(*(const __half2*)&u.x);
    float2 b = __half22float2(*(const __half2*)&u.y);
    acc.x = fmaf(a.x, n, acc.x); acc.y = fmaf(a.y, n, acc.y);
    acc.z = fmaf(b.x, n, acc.z); acc.w = fmaf(b.y, n, acc.w);
}

__global__ __launch_bounds__(256)
void rgcn_gather_kernel(float* __restrict__ out)
{
    const int node = blockIdx.x * 4 + (threadIdx.x >> 6);
    const int lane = threadIdx.x & 63;
    if (node >= N_NODES) return;

    const int beg = g_row[node];
    const int end = g_row[node + 1];

    float4 acc = make_float4(0.f, 0.f, 0.f, 0.f);
    int i = beg;
    for (; i + 3 < end; i += 4) {
        int2 e0 = g_es[i], e1 = g_es[i + 1], e2 = g_es[i + 2], e3 = g_es[i + 3];
        const uint2 u0 = ((const uint2*)(g_T + ((size_t)(e0.x >> 16) * N_NODES + (e0.x & 0xFFFF)) * OUT_FEAT))[lane];
        const uint2 u1 = ((const uint2*)(g_T + ((size_t)(e1.x >> 16) * N_NODES + (e1.x & 0xFFFF)) * OUT_FEAT))[lane];
        const uint2 u2 = ((const uint2*)(g_T + ((size_t)(e2.x >> 16) * N_NODES + (e2.x & 0xFFFF)) * OUT_FEAT))[lane];
        const uint2 u3 = ((const uint2*)(g_T + ((size_t)(e3.x >> 16) * N_NODES + (e3.x & 0xFFFF)) * OUT_FEAT))[lane];
        gacc(acc, u0, __int_as_float(e0.y));
        gacc(acc, u1, __int_as_float(e1.y));
        gacc(acc, u2, __int_as_float(e2.y));
        gacc(acc, u3, __int_as_float(e3.y));
    }
    for (; i < end; i++) {
        int2 e0 = g_es[i];
        const uint2 u0 = ((const uint2*)(g_T + ((size_t)(e0.x >> 16) * N_NODES + (e0.x & 0xFFFF)) * OUT_FEAT))[lane];
        gacc(acc, u0, __int_as_float(e0.y));
    }

    ((float4*)(out + (size_t)node * OUT_FEAT))[lane] = acc;
}

// ---------------------------------------------------------------------------
// Launch
// ---------------------------------------------------------------------------
extern "C" void kernel_launch(void* const* d_in, const int* in_sizes, int n_in,
                              void* d_out, int out_size)
{
    const float* h        = (const float*)d_in[0];
    const float* weight   = (const float*)d_in[1];
    const float* norm     = (const float*)d_in[2];
    const int*   src      = (const int*)d_in[3];
    const int*   dst      = (const int*)d_in[4];
    const int*   rel_type = (const int*)d_in[5];
    float*       out      = (float*)d_out;

    const int E = in_sizes[2];  // 320000

    conv_h_zero_kernel<<<(N_NODES * IN_FEAT + 255) / 256, 256>>>(h);
    conv_wt_kernel<<<dim3(8, 8, NUM_RELS), dim3(32, 32)>>>(weight);

    mark_kernel<<<(E + 255) / 256, 256>>>(src, dst, rel_type, E);
    compact_kernel<<<(USED_WORDS + 7) / 8, 256>>>();
    csr_scan_kernel<<<1, 1024>>>();
    csr_fill_kernel<<<(E + 255) / 256, 256>>>(src, dst, rel_type, norm, E);

    cudaFuncSetAttribute(rgcn_gemm_hmma_kernel,
                         cudaFuncAttributeMaxDynamicSharedMemorySize, SM_TOTAL);
    rgcn_gemm_hmma_kernel<<<dim3(OUT_FEAT / BN, M_TILES, NUM_RELS), GEMM_THREADS, SM_TOTAL>>>();

    rgcn_gather_kernel<<<(N_NODES + 3) / 4, 256>>>(out);
}

// round 15
// speedup vs baseline: 2.6335x; 1.0285x over previous
#include <cuda_runtime.h>
#include <cuda_fp16.h>
#include <cstdint>

// ---------------------------------------------------------------------------
// Problem constants
// ---------------------------------------------------------------------------
#define N_NODES  20000
#define N_EDGES  320000
#define NUM_RELS 16
#define IN_FEAT  256
#define OUT_FEAT 256
#define USED_WORDS (NUM_RELS * N_NODES / 32)   // 10000
#define WORDS_PER_REL (N_NODES / 32)           // 625

// ---------------------------------------------------------------------------
// Device scratch (static globals: allocation-guard safe)
// ---------------------------------------------------------------------------
__device__ __align__(16) __half g_T[(size_t)NUM_RELS * N_NODES * OUT_FEAT];   // 164 MB
__device__ __align__(16) __half g_h16[(size_t)N_NODES * IN_FEAT];             // 10 MB
__device__ __align__(16) __half g_wt16[(size_t)NUM_RELS * OUT_FEAT * IN_FEAT]; // [r][n][k], 2 MB

// CSR-by-dst scratch
__device__ int  g_cnt[N_NODES];
__device__ int  g_fill[N_NODES];
__device__ int  g_row[N_NODES + 1];
__device__ int2 g_es[N_EDGES];   // {src | (rel<<16), bitcast(norm)} sorted by dst

// (rel, src) usage compaction (bitmask)
__device__ unsigned int g_usedw[USED_WORDS];   // 40 KB, L2-resident
__device__ int g_rcnt[NUM_RELS];
__device__ int g_list[NUM_RELS * N_NODES];     // per-rel used-src lists

// ---------------------------------------------------------------------------
// PTX helpers (arch-agnostic: ldmatrix / mma.sync / cp.async only)
// ---------------------------------------------------------------------------
__device__ __forceinline__ uint32_t smem_u32(const void* p) {
    uint32_t a;
    asm("{ .reg .u64 t; cvta.to.shared.u64 t, %1; cvt.u32.u64 %0, t; }" : "=r"(a) : "l"(p));
    return a;
}

#define LDSM_X4(r, addr) \
    asm volatile("ldmatrix.sync.aligned.m8n8.x4.shared.b16 {%0,%1,%2,%3}, [%4];" \
        : "=r"((r)[0]), "=r"((r)[1]), "=r"((r)[2]), "=r"((r)[3]) : "r"(addr))

#define MMA_F16(d, a, b0, b1) \
    asm volatile("mma.sync.aligned.m16n8k16.row.col.f32.f16.f16.f32 " \
        "{%0,%1,%2,%3}, {%4,%5,%6,%7}, {%8,%9}, {%0,%1,%2,%3};" \
        : "+f"((d)[0]), "+f"((d)[1]), "+f"((d)[2]), "+f"((d)[3]) \
        : "r"((a)[0]), "r"((a)[1]), "r"((a)[2]), "r"((a)[3]), "r"(b0), "r"(b1))

#define CP_ASYNC16(saddr, gptr, nbytes) \
    asm volatile("cp.async.cg.shared.global [%0], [%1], 16, %2;" \
        :: "r"(saddr), "l"(gptr), "r"(nbytes))
#define CP_COMMIT() asm volatile("cp.async.commit_group;" ::: "memory")
#define CP_WAIT(n)  asm volatile("cp.async.wait_group %0;" :: "n"(n) : "memory")

// ---------------------------------------------------------------------------
// Kernel A (fused): convert h to fp16 + zero all counters/flags
// ---------------------------------------------------------------------------
__global__ void conv_h_zero_kernel(const float* __restrict__ h)
{
    int i = blockIdx.x * 256 + threadIdx.x;
    if (i < N_NODES * IN_FEAT)
        g_h16[i] = __float2half_rn(h[i]);
    if (i < N_NODES) { g_cnt[i] = 0; g_fill[i] = 0; }
    if (i < USED_WORDS) g_usedw[i] = 0u;
}

// ---------------------------------------------------------------------------
// Kernel B: transpose + convert W:  Wt[r][n][k] = W[r][k][n], fp16
// ---------------------------------------------------------------------------
__global__ void conv_wt_kernel(const float* __restrict__ W)
{
    __shared__ float tile[32][33];
    int r  = blockIdx.z;
    int k0 = blockIdx.x * 32;
    int n0 = blockIdx.y * 32;
    tile[threadIdx.y][threadIdx.x] =
        W[(size_t)r * 65536 + (size_t)(k0 + threadIdx.y) * 256 + n0 + threadIdx.x];
    __syncthreads();
    float x = tile[threadIdx.x][threadIdx.y];   // = W[r][k0+tx][n0+ty]
    size_t oi = (size_t)r * 65536 + (size_t)(n0 + threadIdx.y) * 256 + k0 + threadIdx.x;
    g_wt16[oi] = __float2half_rn(x);
}

// ---------------------------------------------------------------------------
// Mark pass (fused): dst histogram + (rel,src) usage bitmask
// ---------------------------------------------------------------------------
__global__ void mark_kernel(const int* __restrict__ src,
                            const int* __restrict__ dst,
                            const int* __restrict__ rel_type, int E)
{
    int e = blockIdx.x * 256 + threadIdx.x;
    if (e < E) {
        atomicAdd(&g_cnt[dst[e]], 1);
        int idx = rel_type[e] * N_NODES + src[e];
        atomicOr(&g_usedw[idx >> 5], 1u << (idx & 31));
    }
}

// ---------------------------------------------------------------------------
// Compact pass: ATOMIC-FREE.  One block per rel; block-local prefix scan
// over that rel's 625 bitmask words; writes g_rcnt[r] directly.
// ---------------------------------------------------------------------------
__global__ __launch_bounds__(256)
void compact_kernel()
{
    __shared__ int warp_sums[8];
    const int r = blockIdx.x;
    const int t = threadIdx.x;
    const int lane = t & 31, wrp = t >> 5;
    const unsigned* uw = g_usedw + r * WORDS_PER_REL;

    // Each thread owns words t, t+256, t+512 (625 = 256+256+113)
    unsigned w0 = uw[t];
    unsigned w1 = uw[t + 256];
    unsigned w2 = (t + 512 < WORDS_PER_REL) ? uw[t + 512] : 0u;
    int cnt = __popc(w0) + __popc(w1) + __popc(w2);

    // Inclusive warp scan
    int v = cnt;
    #pragma unroll
    for (int off = 1; off < 32; off <<= 1) {
        int u = __shfl_up_sync(0xFFFFFFFFu, v, off);
        if (lane >= off) v += u;
    }
    if (lane == 31) warp_sums[wrp] = v;
    __syncthreads();
    if (wrp == 0) {
        int s = (lane < 8) ? warp_sums[lane] : 0;
        #pragma unroll
        for (int off = 1; off < 8; off <<= 1) {
            int u = __shfl_up_sync(0xFFFFFFFFu, s, off);
            if (lane >= off) s += u;
        }
        if (lane < 8) warp_sums[lane] = s;
    }
    __syncthreads();

    int base = (v - cnt) + (wrp > 0 ? warp_sums[wrp - 1] : 0);
    int* lst = g_list + r * N_NODES;
    int o = base;
    unsigned m = w0; int s0 = t * 32;
    while (m) { int b = __ffs(m) - 1; lst[o++] = s0 + b; m &= m - 1; }
    m = w1; s0 = (t + 256) * 32;
    while (m) { int b = __ffs(m) - 1; lst[o++] = s0 + b; m &= m - 1; }
    m = w2; s0 = (t + 512) * 32;
    while (m) { int b = __ffs(m) - 1; lst[o++] = s0 + b; m &= m - 1; }

    if (t == 0) g_rcnt[r] = warp_sums[7];
}

// ---------------------------------------------------------------------------
// Single-block exclusive scan of g_cnt -> g_row (1024 threads, CH=20).
// ---------------------------------------------------------------------------
__global__ void csr_scan_kernel()
{
    __shared__ int ssum[1024];
    const int t  = threadIdx.x;
    const int CH = (N_NODES + 1023) / 1024;   // 20
    const int base = t * CH;

    int s = 0;
    for (int i = 0; i < CH; i++) {
        int idx = base + i;
        if (idx < N_NODES) s += g_cnt[idx];
    }
    ssum[t] = s;
    __syncthreads();
    for (int off = 1; off < 1024; off <<= 1) {
        int v = (t >= off) ? ssum[t - off] : 0;
        __syncthreads();
        ssum[t] += v;
        __syncthreads();
    }
    int run = (t > 0) ? ssum[t - 1] : 0;
    for (int i = 0; i < CH; i++) {
        int idx = base + i;
        if (idx < N_NODES) { g_row[idx] = run; run += g_cnt[idx]; }
    }
    if (t == 1023) g_row[N_NODES] = ssum[1023];
}

__global__ void csr_fill_kernel(const int* __restrict__ src,
                                const int* __restrict__ dst,
                                const int* __restrict__ rel_type,
                                const float* __restrict__ norm, int E)
{
    int e = blockIdx.x * 256 + threadIdx.x;
    if (e < E) {
        int d = dst[e];
        int pos = g_row[d] + atomicAdd(&g_fill[d], 1);
        g_es[pos] = make_int2(src[e] | (rel_type[e] << 16), __float_as_int(norm[e]));
    }
}

// ---------------------------------------------------------------------------
// Kernel C: fp16 HMMA GEMM over COMPACTED rows.
// CTA 128x128, 4 warps (2m x 2n), warp tile 64x64.
// BKC=64, NSTAGE=3 (one __syncthreads per 64-chunk), 2 CTAs/SM.
// ---------------------------------------------------------------------------
#define BM 128
#define BN 128
#define BKC 64
#define NCHUNK (IN_FEAT / BKC)      // 4
#define A_STRIDE 144                // 128B payload + 16B pad (conflict-free)
#define TILE_BYTES (128 * A_STRIDE) // 18432 per tile
#define OFF_A 0
#define OFF_B TILE_BYTES
#define BUF_BYTES (2 * TILE_BYTES)  // 36864
#define NSTAGE 3
#define SM_TOTAL (NSTAGE * BUF_BYTES)  // 110592 (x2 CTA = 221184 <= 228KB)
#define GEMM_THREADS 128

#define M_TILES ((N_NODES + BM - 1) / BM)   // 157 (upper bound; CTAs early-exit)

__global__ __launch_bounds__(GEMM_THREADS, 2)
void rgcn_gemm_hmma_kernel()
{
    const int rel = blockIdx.z;
    const int m0  = blockIdx.y * BM;
    const int cnt = g_rcnt[rel];
    if (m0 >= cnt) return;

    extern __shared__ char smem[];
    __shared__ int srows[BM];
    const uint32_t smem_base = smem_u32(smem);
    const int tid  = threadIdx.x;
    const int wid  = tid >> 5;
    const int lane = tid & 31;
    const int wm   = wid >> 1;   // 0..1
    const int wn   = wid & 1;    // 0..1

    const int n0 = blockIdx.x * BN;

    if (tid < BM) {
        int li = m0 + tid;
        srows[tid] = (li < cnt) ? g_list[rel * N_NODES + li] : -1;
    }
    __syncthreads();

    const __half* A = g_h16;
    const __half* B = g_wt16 + (size_t)rel * OUT_FEAT * IN_FEAT;

    float acc[4][8][4];   // mi x nf x frag = 128 regs
    #pragma unroll
    for (int i = 0; i < 4; i++)
        #pragma unroll
        for (int j = 0; j < 8; j++)
            #pragma unroll
            for (int k = 0; k < 4; k++)
                acc[i][j][k] = 0.0f;

    const uint32_t aoff = (uint32_t)((wm * 64 + (lane & 15)) * A_STRIDE + (lane >> 4) * 16);
    const uint32_t boff = (uint32_t)((wn * 64 + ((lane >> 4) << 3) + (lane & 7)) * A_STRIDE +
                                     ((lane >> 3) & 1) * 16);

    const uint32_t sb[NSTAGE] = { smem_base, smem_base + BUF_BYTES, smem_base + 2 * BUF_BYTES };

    // Chunk loader: each tile = 128 rows x 8 16B-quads = 1024 segs -> 8 iters
    #define LOAD_CHUNK(sbuf, k0) do {                                            \
        _Pragma("unroll")                                                        \
        for (int it = 0; it < 8; it++) {                                         \
            int seg = tid + it * GEMM_THREADS;                                   \
            int row = seg >> 3;                                                  \
            int q   = seg & 7;                                                   \
            uint32_t so = (uint32_t)(row * A_STRIDE + q * 16);                   \
            int sr  = srows[row];                                                \
            int okA = (sr >= 0) ? 16 : 0;                                        \
            int ar  = (sr >= 0) ? sr : 0;                                        \
            CP_ASYNC16((sbuf) + OFF_A + so, A + (size_t)ar * IN_FEAT + (k0) + q * 8, okA); \
            CP_ASYNC16((sbuf) + OFF_B + so, B + (size_t)(n0 + row) * IN_FEAT + (k0) + q * 8, 16); \
        }                                                                        \
    } while (0)

    LOAD_CHUNK(sb[0], 0);
    CP_COMMIT();
    LOAD_CHUNK(sb[1], BKC);
    CP_COMMIT();

    for (int c = 0; c < NCHUNK; c++) {
        CP_WAIT(1);            // chunk c arrived (c+1 may still be in flight)
        __syncthreads();       // single barrier per chunk

        const uint32_t buf = sb[c % NSTAGE];
        #pragma unroll
        for (int s = 0; s < 4; s++) {          // four k16 steps per 64-chunk
            uint32_t Af[4][4], Bf[4][4];
            #pragma unroll
            for (int mi = 0; mi < 4; mi++) {
                uint32_t ad = buf + aoff + (uint32_t)(mi * 16 * A_STRIDE + s * 32);
                LDSM_X4(Af[mi], ad + OFF_A);
            }
            #pragma unroll
            for (int nj = 0; nj < 4; nj++) {
                uint32_t bd = buf + boff + (uint32_t)(nj * 16 * A_STRIDE + s * 32);
                LDSM_X4(Bf[nj], bd + OFF_B);
            }
            #pragma unroll
            for (int mi = 0; mi < 4; mi++) {
                #pragma unroll
                for (int nf = 0; nf < 8; nf++) {
                    const int nj = nf >> 1, p = (nf & 1) * 2;
                    MMA_F16(acc[mi][nf], Af[mi], Bf[nj][p], Bf[nj][p + 1]);
                }
            }
        }

        // Refill stage (c+2)%NSTAGE (== stage of chunk c-1; all warps passed
        // the barrier above after finishing chunk c-1's compute).
        if (c + 2 < NCHUNK)
            LOAD_CHUNK(sb[(c + 2) % NSTAGE], (c + 2) * BKC);
        CP_COMMIT();           // uniform group count (empty groups legal)
    }
    #undef LOAD_CHUNK

    // Epilogue: indirect store, fp32 acc -> fp16 T[rel][src].
    const int g  = lane >> 2;
    const int tg = lane & 3;
    __half* C = g_T + (size_t)rel * N_NODES * OUT_FEAT;
    #pragma unroll
    for (int mi = 0; mi < 4; mi++) {
        const int lr0 = wm * 64 + mi * 16 + g;
        const int sr0 = srows[lr0];
        const int sr1 = srows[lr0 + 8];
        #pragma unroll
        for (int nf = 0; nf < 8; nf++) {
            const int col = n0 + wn * 64 + nf * 8 + tg * 2;
            if (sr0 >= 0)
                *(__half2*)(C + (size_t)sr0 * OUT_FEAT + col) =
                    __floats2half2_rn(acc[mi][nf][0], acc[mi][nf][1]);
            if (sr1 >= 0)
                *(__half2*)(C + (size_t)sr1 * OUT_FEAT + col) =
                    __floats2half2_rn(acc[mi][nf][2], acc[mi][nf][3]);
        }
    }
}

// ---------------------------------------------------------------------------
// Kernel D: atomic-free gather over fp16 T.  64 threads per dst node,
// 4-deep MLP unroll.
// ---------------------------------------------------------------------------
__device__ __forceinline__ void gacc(float4& acc, const uint2& u, float n)
{
    float2 a = __half22float2(*(const __half2*)&u.x);
    float2 b = __half22float2(*(const __half2*)&u.y);
    acc.x = fmaf(a.x, n, acc.x); acc.y = fmaf(a.y, n, acc.y);
    acc.z = fmaf(b.x, n, acc.z); acc.w = fmaf(b.y, n, acc.w);
}

__global__ __launch_bounds__(256)
void rgcn_gather_kernel(float* __restrict__ out)
{
    const int node = blockIdx.x * 4 + (threadIdx.x >> 6);
    const int lane = threadIdx.x & 63;
    if (node >= N_NODES) return;

    const int beg = g_row[node];
    const int end = g_row[node + 1];

    float4 acc = make_float4(0.f, 0.f, 0.f, 0.f);
    int i = beg;
    for (; i + 3 < end; i += 4) {
        int2 e0 = g_es[i], e1 = g_es[i + 1], e2 = g_es[i + 2], e3 = g_es[i + 3];
        const uint2 u0 = ((const uint2*)(g_T + ((size_t)(e0.x >> 16) * N_NODES + (e0.x & 0xFFFF)) * OUT_FEAT))[lane];
        const uint2 u1 = ((const uint2*)(g_T + ((size_t)(e1.x >> 16) * N_NODES + (e1.x & 0xFFFF)) * OUT_FEAT))[lane];
        const uint2 u2 = ((const uint2*)(g_T + ((size_t)(e2.x >> 16) * N_NODES + (e2.x & 0xFFFF)) * OUT_FEAT))[lane];
        const uint2 u3 = ((const uint2*)(g_T + ((size_t)(e3.x >> 16) * N_NODES + (e3.x & 0xFFFF)) * OUT_FEAT))[lane];
        gacc(acc, u0, __int_as_float(e0.y));
        gacc(acc, u1, __int_as_float(e1.y));
        gacc(acc, u2, __int_as_float(e2.y));
        gacc(acc, u3, __int_as_float(e3.y));
    }
    for (; i < end; i++) {
        int2 e0 = g_es[i];
        const uint2 u0 = ((const uint2*)(g_T + ((size_t)(e0.x >> 16) * N_NODES + (e0.x & 0xFFFF)) * OUT_FEAT))[lane];
        gacc(acc, u0, __int_as_float(e0.y));
    }

    ((float4*)(out + (size_t)node * OUT_FEAT))[lane] = acc;
}

// ---------------------------------------------------------------------------
// Launch
// ---------------------------------------------------------------------------
extern "C" void kernel_launch(void* const* d_in, const int* in_sizes, int n_in,
                              void* d_out, int out_size)
{
    const float* h        = (const float*)d_in[0];
    const float* weight   = (const float*)d_in[1];
    const float* norm     = (const float*)d_in[2];
    const int*   src      = (const int*)d_in[3];
    const int*   dst      = (const int*)d_in[4];
    const int*   rel_type = (const int*)d_in[5];
    float*       out      = (float*)d_out;

    const int E = in_sizes[2];  // 320000

    conv_h_zero_kernel<<<(N_NODES * IN_FEAT + 255) / 256, 256>>>(h);
    conv_wt_kernel<<<dim3(8, 8, NUM_RELS), dim3(32, 32)>>>(weight);

    mark_kernel<<<(E + 255) / 256, 256>>>(src, dst, rel_type, E);
    compact_kernel<<<NUM_RELS, 256>>>();
    csr_scan_kernel<<<1, 1024>>>();
    csr_fill_kernel<<<(E + 255) / 256, 256>>>(src, dst, rel_type, norm, E);

    cudaFuncSetAttribute(rgcn_gemm_hmma_kernel,
                         cudaFuncAttributeMaxDynamicSharedMemorySize, SM_TOTAL);
    rgcn_gemm_hmma_kernel<<<dim3(OUT_FEAT / BN, M_TILES, NUM_RELS), GEMM_THREADS, SM_TOTAL>>>();

    rgcn_gather_kernel<<<(N_NODES + 3) / 4, 256>>>(out);
}

// round 16
// speedup vs baseline: 2.7043x; 1.0269x over previous
#include <cuda_runtime.h>
#include <cuda_fp16.h>
#include <cstdint>

// ---------------------------------------------------------------------------
// Problem constants
// ---------------------------------------------------------------------------
#define N_NODES  20000
#define N_EDGES  320000
#define NUM_RELS 16
#define IN_FEAT  256
#define OUT_FEAT 256
#define USED_WORDS (NUM_RELS * N_NODES / 32)   // 10000
#define WORDS_PER_REL (N_NODES / 32)           // 625
#define COMPACT_CHUNKS 8
#define WORDS_PER_CHUNK 80                     // 8*80=640 >= 625

// ---------------------------------------------------------------------------
// Device scratch (static globals: allocation-guard safe)
// ---------------------------------------------------------------------------
__device__ __align__(16) __half g_T[(size_t)NUM_RELS * N_NODES * OUT_FEAT];   // 164 MB
__device__ __align__(16) __half g_h16[(size_t)N_NODES * IN_FEAT];             // 10 MB
__device__ __align__(16) __half g_wt16[(size_t)NUM_RELS * OUT_FEAT * IN_FEAT]; // [r][n][k], 2 MB

// CSR-by-dst scratch
__device__ int  g_cnt[N_NODES];
__device__ int  g_fill[N_NODES];
__device__ int  g_row[N_NODES + 1];
__device__ int2 g_es[N_EDGES];   // {src | (rel<<16), bitcast(norm)} sorted by dst

// (rel, src) usage compaction (bitmask)
__device__ unsigned int g_usedw[USED_WORDS];   // 40 KB, L2-resident
__device__ int g_rcnt[NUM_RELS];
__device__ int g_list[NUM_RELS * N_NODES];     // per-rel used-src lists

// ---------------------------------------------------------------------------
// PTX helpers (arch-agnostic: ldmatrix / mma.sync / cp.async only)
// ---------------------------------------------------------------------------
__device__ __forceinline__ uint32_t smem_u32(const void* p) {
    uint32_t a;
    asm("{ .reg .u64 t; cvta.to.shared.u64 t, %1; cvt.u32.u64 %0, t; }" : "=r"(a) : "l"(p));
    return a;
}

#define LDSM_X4(r, addr) \
    asm volatile("ldmatrix.sync.aligned.m8n8.x4.shared.b16 {%0,%1,%2,%3}, [%4];" \
        : "=r"((r)[0]), "=r"((r)[1]), "=r"((r)[2]), "=r"((r)[3]) : "r"(addr))

#define MMA_F16(d, a, b0, b1) \
    asm volatile("mma.sync.aligned.m16n8k16.row.col.f32.f16.f16.f32 " \
        "{%0,%1,%2,%3}, {%4,%5,%6,%7}, {%8,%9}, {%0,%1,%2,%3};" \
        : "+f"((d)[0]), "+f"((d)[1]), "+f"((d)[2]), "+f"((d)[3]) \
        : "r"((a)[0]), "r"((a)[1]), "r"((a)[2]), "r"((a)[3]), "r"(b0), "r"(b1))

#define CP_ASYNC16(saddr, gptr, nbytes) \
    asm volatile("cp.async.cg.shared.global [%0], [%1], 16, %2;" \
        :: "r"(saddr), "l"(gptr), "r"(nbytes))
#define CP_COMMIT() asm volatile("cp.async.commit_group;" ::: "memory")
#define CP_WAIT(n)  asm volatile("cp.async.wait_group %0;" :: "n"(n) : "memory")

// ---------------------------------------------------------------------------
// Kernel A (fused): convert h to fp16 + zero all counters/flags
// ---------------------------------------------------------------------------
__global__ void conv_h_zero_kernel(const float* __restrict__ h)
{
    int i = blockIdx.x * 256 + threadIdx.x;
    if (i < N_NODES * IN_FEAT)
        g_h16[i] = __float2half_rn(h[i]);
    if (i < N_NODES) { g_cnt[i] = 0; g_fill[i] = 0; }
    if (i < USED_WORDS) g_usedw[i] = 0u;
    if (i < NUM_RELS) g_rcnt[i] = 0;
}

// ---------------------------------------------------------------------------
// Kernel B: transpose + convert W:  Wt[r][n][k] = W[r][k][n], fp16
// ---------------------------------------------------------------------------
__global__ void conv_wt_kernel(const float* __restrict__ W)
{
    __shared__ float tile[32][33];
    int r  = blockIdx.z;
    int k0 = blockIdx.x * 32;
    int n0 = blockIdx.y * 32;
    tile[threadIdx.y][threadIdx.x] =
        W[(size_t)r * 65536 + (size_t)(k0 + threadIdx.y) * 256 + n0 + threadIdx.x];
    __syncthreads();
    float x = tile[threadIdx.x][threadIdx.y];   // = W[r][k0+tx][n0+ty]
    size_t oi = (size_t)r * 65536 + (size_t)(n0 + threadIdx.y) * 256 + k0 + threadIdx.x;
    g_wt16[oi] = __float2half_rn(x);
}

// ---------------------------------------------------------------------------
// Mark pass: dst histogram + usage bitmask, 4 edges/thread (int4 ILP).
// E = 320000 is divisible by 4.
// ---------------------------------------------------------------------------
__global__ void mark_kernel(const int4* __restrict__ src4,
                            const int4* __restrict__ dst4,
                            const int4* __restrict__ rel4, int E4)
{
    int e = blockIdx.x * 256 + threadIdx.x;
    if (e < E4) {
        int4 d = dst4[e];
        int4 s = src4[e];
        int4 r = rel4[e];
        atomicAdd(&g_cnt[d.x], 1);
        atomicAdd(&g_cnt[d.y], 1);
        atomicAdd(&g_cnt[d.z], 1);
        atomicAdd(&g_cnt[d.w], 1);
        int i0 = r.x * N_NODES + s.x;
        int i1 = r.y * N_NODES + s.y;
        int i2 = r.z * N_NODES + s.z;
        int i3 = r.w * N_NODES + s.w;
        atomicOr(&g_usedw[i0 >> 5], 1u << (i0 & 31));
        atomicOr(&g_usedw[i1 >> 5], 1u << (i1 & 31));
        atomicOr(&g_usedw[i2 >> 5], 1u << (i2 & 31));
        atomicOr(&g_usedw[i3 >> 5], 1u << (i3 & 31));
    }
}

// ---------------------------------------------------------------------------
// Compact pass v3: grid (COMPACT_CHUNKS, NUM_RELS) = 128 blocks, 128 thr.
// Block-local scan over <=80 words; ONE atomicAdd per block for the base.
// List order within a rel is arbitrary (correctness doesn't depend on it).
// ---------------------------------------------------------------------------
__global__ __launch_bounds__(128)
void compact_kernel()
{
    __shared__ int wsum[4];
    __shared__ int blockbase;
    const int r = blockIdx.y;
    const int t = threadIdx.x;                    // 0..127
    const int w = blockIdx.x * WORDS_PER_CHUNK + t;
    const int lane = t & 31, wrp = t >> 5;

    unsigned word = (t < WORDS_PER_CHUNK && w < WORDS_PER_REL)
                    ? g_usedw[r * WORDS_PER_REL + w] : 0u;
    int cnt = __popc(word);

    // Inclusive warp scan
    int v = cnt;
    #pragma unroll
    for (int off = 1; off < 32; off <<= 1) {
        int u = __shfl_up_sync(0xFFFFFFFFu, v, off);
        if (lane >= off) v += u;
    }
    if (lane == 31) wsum[wrp] = v;
    __syncthreads();
    if (t == 0) {
        int s = 0;
        #pragma unroll
        for (int i = 0; i < 4; i++) { int x = wsum[i]; wsum[i] = s; s += x; }
        blockbase = s ? atomicAdd(&g_rcnt[r], s) : 0;
    }
    __syncthreads();

    if (word) {
        int o = blockbase + wsum[wrp] + (v - cnt);
        int* lst = g_list + r * N_NODES;
        int s0 = w * 32;
        unsigned m = word;
        while (m) { int b = __ffs(m) - 1; lst[o++] = s0 + b; m &= m - 1; }
    }
}

// ---------------------------------------------------------------------------
// Single-block exclusive scan of g_cnt -> g_row (1024 threads, CH=20).
// ---------------------------------------------------------------------------
__global__ void csr_scan_kernel()
{
    __shared__ int ssum[1024];
    const int t  = threadIdx.x;
    const int CH = (N_NODES + 1023) / 1024;   // 20
    const int base = t * CH;

    int s = 0;
    for (int i = 0; i < CH; i++) {
        int idx = base + i;
        if (idx < N_NODES) s += g_cnt[idx];
    }
    ssum[t] = s;
    __syncthreads();
    for (int off = 1; off < 1024; off <<= 1) {
        int v = (t >= off) ? ssum[t - off] : 0;
        __syncthreads();
        ssum[t] += v;
        __syncthreads();
    }
    int run = (t > 0) ? ssum[t - 1] : 0;
    for (int i = 0; i < CH; i++) {
        int idx = base + i;
        if (idx < N_NODES) { g_row[idx] = run; run += g_cnt[idx]; }
    }
    if (t == 1023) g_row[N_NODES] = ssum[1023];
}

// ---------------------------------------------------------------------------
// Fill pass: 4 edges/thread (int4/float4 ILP).
// ---------------------------------------------------------------------------
__global__ void csr_fill_kernel(const int4* __restrict__ src4,
                                const int4* __restrict__ dst4,
                                const int4* __restrict__ rel4,
                                const float4* __restrict__ norm4, int E4)
{
    int e = blockIdx.x * 256 + threadIdx.x;
    if (e < E4) {
        int4   d = dst4[e];
        int4   s = src4[e];
        int4   r = rel4[e];
        float4 n = norm4[e];
        int p0 = g_row[d.x] + atomicAdd(&g_fill[d.x], 1);
        int p1 = g_row[d.y] + atomicAdd(&g_fill[d.y], 1);
        int p2 = g_row[d.z] + atomicAdd(&g_fill[d.z], 1);
        int p3 = g_row[d.w] + atomicAdd(&g_fill[d.w], 1);
        g_es[p0] = make_int2(s.x | (r.x << 16), __float_as_int(n.x));
        g_es[p1] = make_int2(s.y | (r.y << 16), __float_as_int(n.y));
        g_es[p2] = make_int2(s.z | (r.z << 16), __float_as_int(n.z));
        g_es[p3] = make_int2(s.w | (r.w << 16), __float_as_int(n.w));
    }
}

// ---------------------------------------------------------------------------
// Kernel C: fp16 HMMA GEMM over COMPACTED rows.
// CTA 128x128, 4 warps (2m x 2n), warp tile 64x64.
// BKC=64, NSTAGE=3 (one __syncthreads per 64-chunk), 2 CTAs/SM.
// ---------------------------------------------------------------------------
#define BM 128
#define BN 128
#define BKC 64
#define NCHUNK (IN_FEAT / BKC)      // 4
#define A_STRIDE 144                // 128B payload + 16B pad (conflict-free)
#define TILE_BYTES (128 * A_STRIDE) // 18432 per tile
#define OFF_A 0
#define OFF_B TILE_BYTES
#define BUF_BYTES (2 * TILE_BYTES)  // 36864
#define NSTAGE 3
#define SM_TOTAL (NSTAGE * BUF_BYTES)  // 110592 (x2 CTA = 221184 <= 228KB)
#define GEMM_THREADS 128

#define M_TILES ((N_NODES + BM - 1) / BM)   // 157 (upper bound; CTAs early-exit)

__global__ __launch_bounds__(GEMM_THREADS, 2)
void rgcn_gemm_hmma_kernel()
{
    const int rel = blockIdx.z;
    const int m0  = blockIdx.y * BM;
    const int cnt = g_rcnt[rel];
    if (m0 >= cnt) return;

    extern __shared__ char smem[];
    __shared__ int srows[BM];
    const uint32_t smem_base = smem_u32(smem);
    const int tid  = threadIdx.x;
    const int wid  = tid >> 5;
    const int lane = tid & 31;
    const int wm   = wid >> 1;   // 0..1
    const int wn   = wid & 1;    // 0..1

    const int n0 = blockIdx.x * BN;

    if (tid < BM) {
        int li = m0 + tid;
        srows[tid] = (li < cnt) ? g_list[rel * N_NODES + li] : -1;
    }
    __syncthreads();

    const __half* A = g_h16;
    const __half* B = g_wt16 + (size_t)rel * OUT_FEAT * IN_FEAT;

    float acc[4][8][4];   // mi x nf x frag = 128 regs
    #pragma unroll
    for (int i = 0; i < 4; i++)
        #pragma unroll
        for (int j = 0; j < 8; j++)
            #pragma unroll
            for (int k = 0; k < 4; k++)
                acc[i][j][k] = 0.0f;

    const uint32_t aoff = (uint32_t)((wm * 64 + (lane & 15)) * A_STRIDE + (lane >> 4) * 16);
    const uint32_t boff = (uint32_t)((wn * 64 + ((lane >> 4) << 3) + (lane & 7)) * A_STRIDE +
                                     ((lane >> 3) & 1) * 16);

    const uint32_t sb[NSTAGE] = { smem_base, smem_base + BUF_BYTES, smem_base + 2 * BUF_BYTES };

    // Chunk loader: each tile = 128 rows x 8 16B-quads = 1024 segs -> 8 iters
    #define LOAD_CHUNK(sbuf, k0) do {                                            \
        _Pragma("unroll")                                                        \
        for (int it = 0; it < 8; it++) {                                         \
            int seg = tid + it * GEMM_THREADS;                                   \
            int row = seg >> 3;                                                  \
            int q   = seg & 7;                                                   \
            uint32_t so = (uint32_t)(row * A_STRIDE + q * 16);                   \
            int sr  = srows[row];                                                \
            int okA = (sr >= 0) ? 16 : 0;                                        \
            int ar  = (sr >= 0) ? sr : 0;                                        \
            CP_ASYNC16((sbuf) + OFF_A + so, A + (size_t)ar * IN_FEAT + (k0) + q * 8, okA); \
            CP_ASYNC16((sbuf) + OFF_B + so, B + (size_t)(n0 + row) * IN_FEAT + (k0) + q * 8, 16); \
        }                                                                        \
    } while (0)

    LOAD_CHUNK(sb[0], 0);
    CP_COMMIT();
    LOAD_CHUNK(sb[1], BKC);
    CP_COMMIT();

    for (int c = 0; c < NCHUNK; c++) {
        CP_WAIT(1);            // chunk c arrived (c+1 may still be in flight)
        __syncthreads();       // single barrier per chunk

        const uint32_t buf = sb[c % NSTAGE];
        #pragma unroll
        for (int s = 0; s < 4; s++) {          // four k16 steps per 64-chunk
            uint32_t Af[4][4], Bf[4][4];
            #pragma unroll
            for (int mi = 0; mi < 4; mi++) {
                uint32_t ad = buf + aoff + (uint32_t)(mi * 16 * A_STRIDE + s * 32);
                LDSM_X4(Af[mi], ad + OFF_A);
            }
            #pragma unroll
            for (int nj = 0; nj < 4; nj++) {
                uint32_t bd = buf + boff + (uint32_t)(nj * 16 * A_STRIDE + s * 32);
                LDSM_X4(Bf[nj], bd + OFF_B);
            }
            #pragma unroll
            for (int mi = 0; mi < 4; mi++) {
                #pragma unroll
                for (int nf = 0; nf < 8; nf++) {
                    const int nj = nf >> 1, p = (nf & 1) * 2;
                    MMA_F16(acc[mi][nf], Af[mi], Bf[nj][p], Bf[nj][p + 1]);
                }
            }
        }

        // Refill stage (c+2)%NSTAGE (== stage of chunk c-1; all warps passed
        // the barrier above after finishing chunk c-1's compute).
        if (c + 2 < NCHUNK)
            LOAD_CHUNK(sb[(c + 2) % NSTAGE], (c + 2) * BKC);
        CP_COMMIT();           // uniform group count (empty groups legal)
    }
    #undef LOAD_CHUNK

    // Epilogue: indirect store, fp32 acc -> fp16 T[rel][src].
    const int g  = lane >> 2;
    const int tg = lane & 3;
    __half* C = g_T + (size_t)rel * N_NODES * OUT_FEAT;
    #pragma unroll
    for (int mi = 0; mi < 4; mi++) {
        const int lr0 = wm * 64 + mi * 16 + g;
        const int sr0 = srows[lr0];
        const int sr1 = srows[lr0 + 8];
        #pragma unroll
        for (int nf = 0; nf < 8; nf++) {
            const int col = n0 + wn * 64 + nf * 8 + tg * 2;
            if (sr0 >= 0)
                *(__half2*)(C + (size_t)sr0 * OUT_FEAT + col) =
                    __floats2half2_rn(acc[mi][nf][0], acc[mi][nf][1]);
            if (sr1 >= 0)
                *(__half2*)(C + (size_t)sr1 * OUT_FEAT + col) =
                    __floats2half2_rn(acc[mi][nf][2], acc[mi][nf][3]);
        }
    }
}

// ---------------------------------------------------------------------------
// Kernel D: atomic-free gather over fp16 T.  64 threads per dst node,
// 4-deep MLP unroll.
// ---------------------------------------------------------------------------
__device__ __forceinline__ void gacc(float4& acc, const uint2& u, float n)
{
    float2 a = __half22float2(*(const __half2*)&u.x);
    float2 b = __half22float2(*(const __half2*)&u.y);
    acc.x = fmaf(a.x, n, acc.x); acc.y = fmaf(a.y, n, acc.y);
    acc.z = fmaf(b.x, n, acc.z); acc.w = fmaf(b.y, n, acc.w);
}

__global__ __launch_bounds__(256)
void rgcn_gather_kernel(float* __restrict__ out)
{
    const int node = blockIdx.x * 4 + (threadIdx.x >> 6);
    const int lane = threadIdx.x & 63;
    if (node >= N_NODES) return;

    const int beg = g_row[node];
    const int end = g_row[node + 1];

    float4 acc = make_float4(0.f, 0.f, 0.f, 0.f);
    int i = beg;
    for (; i + 3 < end; i += 4) {
        int2 e0 = g_es[i], e1 = g_es[i + 1], e2 = g_es[i + 2], e3 = g_es[i + 3];
        const uint2 u0 = ((const uint2*)(g_T + ((size_t)(e0.x >> 16) * N_NODES + (e0.x & 0xFFFF)) * OUT_FEAT))[lane];
        const uint2 u1 = ((const uint2*)(g_T + ((size_t)(e1.x >> 16) * N_NODES + (e1.x & 0xFFFF)) * OUT_FEAT))[lane];
        const uint2 u2 = ((const uint2*)(g_T + ((size_t)(e2.x >> 16) * N_NODES + (e2.x & 0xFFFF)) * OUT_FEAT))[lane];
        const uint2 u3 = ((const uint2*)(g_T + ((size_t)(e3.x >> 16) * N_NODES + (e3.x & 0xFFFF)) * OUT_FEAT))[lane];
        gacc(acc, u0, __int_as_float(e0.y));
        gacc(acc, u1, __int_as_float(e1.y));
        gacc(acc, u2, __int_as_float(e2.y));
        gacc(acc, u3, __int_as_float(e3.y));
    }
    for (; i < end; i++) {
        int2 e0 = g_es[i];
        const uint2 u0 = ((const uint2*)(g_T + ((size_t)(e0.x >> 16) * N_NODES + (e0.x & 0xFFFF)) * OUT_FEAT))[lane];
        gacc(acc, u0, __int_as_float(e0.y));
    }

    ((float4*)(out + (size_t)node * OUT_FEAT))[lane] = acc;
}

// ---------------------------------------------------------------------------
// Launch
// ---------------------------------------------------------------------------
extern "C" void kernel_launch(void* const* d_in, const int* in_sizes, int n_in,
                              void* d_out, int out_size)
{
    const float* h        = (const float*)d_in[0];
    const float* weight   = (const float*)d_in[1];
    const float* norm     = (const float*)d_in[2];
    const int*   src      = (const int*)d_in[3];
    const int*   dst      = (const int*)d_in[4];
    const int*   rel_type = (const int*)d_in[5];
    float*       out      = (float*)d_out;

    const int E  = in_sizes[2];   // 320000
    const int E4 = E / 4;         // 80000 (E divisible by 4)

    conv_h_zero_kernel<<<(N_NODES * IN_FEAT + 255) / 256, 256>>>(h);
    conv_wt_kernel<<<dim3(8, 8, NUM_RELS), dim3(32, 32)>>>(weight);

    mark_kernel<<<(E4 + 255) / 256, 256>>>(
        (const int4*)src, (const int4*)dst, (const int4*)rel_type, E4);
    compact_kernel<<<dim3(COMPACT_CHUNKS, NUM_RELS), 128>>>();
    csr_scan_kernel<<<1, 1024>>>();
    csr_fill_kernel<<<(E4 + 255) / 256, 256>>>(
        (const int4*)src, (const int4*)dst, (const int4*)rel_type,
        (const float4*)norm, E4);

    cudaFuncSetAttribute(rgcn_gemm_hmma_kernel,
                         cudaFuncAttributeMaxDynamicSharedMemorySize, SM_TOTAL);
    rgcn_gemm_hmma_kernel<<<dim3(OUT_FEAT / BN, M_TILES, NUM_RELS), GEMM_THREADS, SM_TOTAL>>>();

    rgcn_gather_kernel<<<(N_NODES + 3) / 4, 256>>>(out);
}